// round 5
// baseline (speedup 1.0000x reference)
#include <cuda_runtime.h>
#include <math.h>

// Problem constants
constexpr int kB  = 4;
constexpr int kS  = 2048;
constexpr int kD  = 1024;
constexpr int kH  = 16;
constexpr int kDK = 64;   // == DV

// Scratch (device globals — no allocation allowed). 4 x 32 MB.
__device__ float g_Q[kB * kH * kS * kDK];   // [B,H,S,DK]
__device__ float g_K[kB * kH * kS * kDK];
__device__ float g_V[kB * kH * kS * kDK];
__device__ float g_CTX[kB * kS * kH * kDK]; // [B,S,H*DV] == row-major [8192,1024]

// ---------------------------------------------------------------------------
// Tiled GEMM: C = A @ W
//   A: [M,K] row-major
//   WMODE 0: W[k*N + n]                              (plain row-major [K,N])
//   WMODE 1: W[(n>>6)*(K*64) + k*64 + (n&63)]        (per-head [H,D,64])
//   OMODE 0: C[r*N + n]
//   OMODE 1: C[((b*kH + h)*kS + s)*64 + dk], r=b*kS+s, h=n>>6, dk=n&63
//   SRC: 0 = use A arg, 1 = g_CTX (resolved in DEVICE code)
//   DST: 0 = g_Q, 1 = g_K, 2 = g_V, 3 = use C arg
// Block: 64x64 output tile, BK=16, 256 threads, 4x4 per thread.
// ---------------------------------------------------------------------------
template <int WMODE, int OMODE, int SRC, int DST>
__global__ __launch_bounds__(256)
void gemm64(const float* __restrict__ Aarg, const float* __restrict__ W,
            float* __restrict__ Carg, int M, int N, int K)
{
    // Resolve scratch symbols on the DEVICE side (host cannot take their address).
    const float* A = (SRC == 1) ? g_CTX : Aarg;
    float* C;
    if      (DST == 0) C = g_Q;
    else if (DST == 1) C = g_K;
    else if (DST == 2) C = g_V;
    else               C = Carg;

    __shared__ __align__(16) float As[16][64];  // [kk][m]
    __shared__ __align__(16) float Bs[16][64];  // [kk][n]

    const int tid = threadIdx.x;
    const int tx  = tid & 15;        // col group
    const int ty  = tid >> 4;        // row group
    const int bm  = blockIdx.y * 64;
    const int bn  = blockIdx.x * 64;

    float acc[4][4];
#pragma unroll
    for (int i = 0; i < 4; i++)
#pragma unroll
        for (int j = 0; j < 4; j++) acc[i][j] = 0.f;

    for (int k0 = 0; k0 < K; k0 += 16) {
        // Load A tile (64 rows x 16 k) -> As[kk][m]
#pragma unroll
        for (int i = 0; i < 4; i++) {
            int e = tid + i * 256;          // 0..1023
            int r = e >> 4, c = e & 15;
            As[c][r] = A[(size_t)(bm + r) * K + (k0 + c)];
        }
        // Load W tile (16 k x 64 n) -> Bs[kk][n]
#pragma unroll
        for (int i = 0; i < 4; i++) {
            int e  = tid + i * 256;
            int kk = e >> 6, n = e & 63;
            int gn = bn + n, gk = k0 + kk;
            float w;
            if (WMODE == 0) w = W[(size_t)gk * N + gn];
            else            w = W[(size_t)(gn >> 6) * (K * 64) + (size_t)gk * 64 + (gn & 63)];
            Bs[kk][n] = w;
        }
        __syncthreads();

#pragma unroll
        for (int kk = 0; kk < 16; kk++) {
            float4 a4 = *(const float4*)&As[kk][ty * 4];
            float4 b4 = *(const float4*)&Bs[kk][tx * 4];
            float a[4] = {a4.x, a4.y, a4.z, a4.w};
            float b[4] = {b4.x, b4.y, b4.z, b4.w};
#pragma unroll
            for (int i = 0; i < 4; i++)
#pragma unroll
                for (int j = 0; j < 4; j++) acc[i][j] += a[i] * b[j];
        }
        __syncthreads();
    }

#pragma unroll
    for (int i = 0; i < 4; i++) {
        int r = bm + ty * 4 + i;
#pragma unroll
        for (int j = 0; j < 4; j++) {
            int n = bn + tx * 4 + j;
            if (OMODE == 0) {
                C[(size_t)r * N + n] = acc[i][j];
            } else {
                int bb = r / kS, ss = r % kS;
                int h = n >> 6, dk = n & 63;
                C[((size_t)(bb * kH + h) * kS + ss) * 64 + dk] = acc[i][j];
            }
        }
    }
}

// ---------------------------------------------------------------------------
// Causal flash attention, fp32.
// Q/K/V: [B,H,S,64] (device globals). Output ctx in [B,S,H*64] layout.
// Block: 128 threads = 128 query rows. K/V tiles of 64 keys in SMEM.
// grid: (S/128, B*H)
// ---------------------------------------------------------------------------
__global__ __launch_bounds__(128)
void flash_attn()
{
    __shared__ __align__(16) float4 Ks[64][16];
    __shared__ __align__(16) float4 Vs[64][16];

    const int tid  = threadIdx.x;
    const int qblk = blockIdx.x;          // 0..15
    const int bh   = blockIdx.y;          // 0..63
    const int b    = bh >> 4;
    const int h    = bh & 15;
    const int qi   = qblk * 128 + tid;    // this thread's query row

    const float* Qbase = g_Q + (size_t)bh * kS * 64;
    const float* Kbase = g_K + (size_t)bh * kS * 64;
    const float* Vbase = g_V + (size_t)bh * kS * 64;

    // Stage Q tile (128 rows) through SMEM (coalesced), then scatter to regs.
    float q[64];
#pragma unroll
    for (int i = 0; i < 8; i++) {
        int e = tid + i * 128;            // 0..1023 : rows 0..63
        int r = e >> 4, c = e & 15;
        Ks[r][c] = ((const float4*)(Qbase + (size_t)(qblk * 128 + r) * 64))[c];
        Vs[r][c] = ((const float4*)(Qbase + (size_t)(qblk * 128 + 64 + r) * 64))[c];
    }
    __syncthreads();
#pragma unroll
    for (int c = 0; c < 16; c++) {
        float4 v = (tid < 64) ? Ks[tid][c] : Vs[tid - 64][c];
        q[c * 4 + 0] = v.x; q[c * 4 + 1] = v.y;
        q[c * 4 + 2] = v.z; q[c * 4 + 3] = v.w;
    }
    __syncthreads();

    float o[64];
#pragma unroll
    for (int d = 0; d < 64; d++) o[d] = 0.f;
    float m = -1e30f, l = 0.f;

    const int ktiles = qblk * 2 + 2;      // 64-key tiles covering keys <= qi_max
    for (int kt = 0; kt < ktiles; kt++) {
        // Load K,V tile (coalesced float4)
#pragma unroll
        for (int i = 0; i < 8; i++) {
            int e = tid + i * 128;
            int r = e >> 4, c = e & 15;
            Ks[r][c] = ((const float4*)(Kbase + (size_t)(kt * 64 + r) * 64))[c];
            Vs[r][c] = ((const float4*)(Vbase + (size_t)(kt * 64 + r) * 64))[c];
        }
        __syncthreads();

        const int kbase = kt * 64;
#pragma unroll 1
        for (int j = 0; j < 64; j++) {
            int kg = kbase + j;
            float s = 0.f;
#pragma unroll
            for (int c = 0; c < 16; c++) {
                float4 kv = Ks[j][c];
                s += q[c * 4 + 0] * kv.x + q[c * 4 + 1] * kv.y
                   + q[c * 4 + 2] * kv.z + q[c * 4 + 3] * kv.w;
            }
            s *= 0.125f;                          // 1/sqrt(64)
            if (kg > qi) s = -1e30f;              // causal mask
            if (s > m) {                          // rare rescale
                float corr = __expf(m - s);
                m = s;
                l *= corr;
#pragma unroll
                for (int d = 0; d < 64; d++) o[d] *= corr;
            }
            float p = __expf(s - m);
            l += p;
#pragma unroll
            for (int c = 0; c < 16; c++) {
                float4 vv = Vs[j][c];
                o[c * 4 + 0] += p * vv.x; o[c * 4 + 1] += p * vv.y;
                o[c * 4 + 2] += p * vv.z; o[c * 4 + 3] += p * vv.w;
            }
        }
        __syncthreads();
    }

    const float inv = 1.f / l;
    float* out = g_CTX + ((size_t)(b * kS + qi) * kH + h) * 64;
#pragma unroll
    for (int c = 0; c < 16; c++) {
        float4 v;
        v.x = o[c * 4 + 0] * inv; v.y = o[c * 4 + 1] * inv;
        v.z = o[c * 4 + 2] * inv; v.w = o[c * 4 + 3] * inv;
        ((float4*)out)[c] = v;
    }
}

// ---------------------------------------------------------------------------
extern "C" void kernel_launch(void* const* d_in, const int* in_sizes, int n_in,
                              void* d_out, int out_size)
{
    const float* x  = (const float*)d_in[0];   // [B,S,D]
    const float* Wq = (const float*)d_in[1];   // [H,D,DK]
    const float* Wk = (const float*)d_in[2];
    const float* Wv = (const float*)d_in[3];
    const float* Wo = (const float*)d_in[4];   // [H*DV, D]
    float* out = (float*)d_out;                // [B,S,D]

    const int M = kB * kS;   // 8192
    const int N = kH * kDK;  // 1024
    const int K = kD;        // 1024

    dim3 ggrid(N / 64, M / 64);   // (16,128)

    // QKV projections (weight [H,D,64], output [B,H,S,64]); destinations are
    // device-global scratch selected INSIDE the kernel via the DST template
    // parameter (host code cannot take the address of a __device__ symbol).
    gemm64<1, 1, 0, 0><<<ggrid, 256>>>(x, Wq, nullptr, M, N, K);  // -> g_Q
    gemm64<1, 1, 0, 1><<<ggrid, 256>>>(x, Wk, nullptr, M, N, K);  // -> g_K
    gemm64<1, 1, 0, 2><<<ggrid, 256>>>(x, Wv, nullptr, M, N, K);  // -> g_V

    // Causal attention -> g_CTX in [B,S,H*DV]
    flash_attn<<<dim3(kS / 128, kB * kH), 128>>>();

    // Output projection: [8192,1024] @ [1024,1024] -> d_out
    gemm64<0, 0, 1, 3><<<ggrid, 256>>>(nullptr, Wo, out, M, kD, kH * kDK);
}

// round 8
// speedup vs baseline: 1.7270x; 1.7270x over previous
#include <cuda_runtime.h>
#include <cuda_bf16.h>
#include <math.h>
#include <stdint.h>

// Problem constants
constexpr int kB  = 4;
constexpr int kS  = 2048;
constexpr int kD  = 1024;
constexpr int kH  = 16;

// ---------------------------------------------------------------------------
// Scratch (device globals — no allocation allowed)
// ---------------------------------------------------------------------------
__device__ float g_Q[kB * kH * kS * 64];    // [B,H,S,64] fp32
__device__ float g_K[kB * kH * kS * 64];
__device__ float g_V[kB * kH * kS * 64];
__device__ float g_CTX[kB * kS * kH * 64];  // [B,S,H*64] fp32 == [8192,1024]

__device__ __nv_bfloat16 g_xhi[kB * kS * kD];   // A split (x or ctx) [8192,1024]
__device__ __nv_bfloat16 g_xlo[kB * kS * kD];
__device__ __nv_bfloat16 g_whi[3 * kD * kD];    // B split, [N<=3072][K=1024] K-major
__device__ __nv_bfloat16 g_wlo[3 * kD * kD];

__device__ __forceinline__ uint32_t smem_u32(const void* p) {
    uint32_t a;
    asm("{ .reg .u64 t; cvta.to.shared.u64 t, %1; cvt.u32.u64 %0, t; }" : "=r"(a) : "l"(p));
    return a;
}

// ---------------------------------------------------------------------------
// Split-conversion kernels
// ---------------------------------------------------------------------------
template <int SRC>  // 0 = arg, 1 = g_CTX
__global__ __launch_bounds__(256)
void cvt_split(const float* __restrict__ src_arg)
{
    const float* src = (SRC == 1) ? g_CTX : src_arg;
    int i = blockIdx.x * 256 + threadIdx.x;       // float4 index, 2M total
    float4 v = ((const float4*)src)[i];
    __nv_bfloat16 h0 = __float2bfloat16(v.x), h1 = __float2bfloat16(v.y);
    __nv_bfloat16 h2 = __float2bfloat16(v.z), h3 = __float2bfloat16(v.w);
    __nv_bfloat16 l0 = __float2bfloat16(v.x - __bfloat162float(h0));
    __nv_bfloat16 l1 = __float2bfloat16(v.y - __bfloat162float(h1));
    __nv_bfloat16 l2 = __float2bfloat16(v.z - __bfloat162float(h2));
    __nv_bfloat16 l3 = __float2bfloat16(v.w - __bfloat162float(h3));
    ((__nv_bfloat162*)g_xhi)[i * 2 + 0] = __nv_bfloat162(h0, h1);
    ((__nv_bfloat162*)g_xhi)[i * 2 + 1] = __nv_bfloat162(h2, h3);
    ((__nv_bfloat162*)g_xlo)[i * 2 + 0] = __nv_bfloat162(l0, l1);
    ((__nv_bfloat162*)g_xlo)[i * 2 + 1] = __nv_bfloat162(l2, l3);
}

// Weights -> g_whi/g_wlo as B[n][k] (K-major) at row offset n_off.
// HEAD 1: W is [H,D,64]:  n = n_off + h*64 + dk, k = d
// HEAD 0: W is [1024,1024] row-major (out = ctx @ W): n = n_off + col, k = row
template <int HEAD>
__global__ __launch_bounds__(256)
void cvt_w(const float* __restrict__ W, int n_off)
{
    int idx = blockIdx.x * 256 + threadIdx.x;     // coalesced read
    float v = W[idx];
    int n, k;
    if (HEAD) { int dk = idx & 63, kk = (idx >> 6) & 1023, h = idx >> 16;
                n = n_off + h * 64 + dk; k = kk; }
    else      { n = n_off + (idx & 1023); k = idx >> 10; }
    __nv_bfloat16 hi = __float2bfloat16(v);
    __nv_bfloat16 lo = __float2bfloat16(v - __bfloat162float(hi));
    g_whi[(size_t)n * 1024 + k] = hi;
    g_wlo[(size_t)n * 1024 + k] = lo;
}

// ---------------------------------------------------------------------------
// HMMA split-bf16 GEMM: C[8192, NB*128] = A @ B^T, fp32-accurate via 3 passes.
// A: g_xhi/g_xlo [8192,1024]; B: g_whi/g_wlo [n][k] K-major.
// CTA tile 128x128, BK=32, 8 warps (warp tile 32x64), 2-stage cp.async.
// OMODE 0: C[row*1024 + n] = Carg.   OMODE 1: scatter to g_Q/g_K/g_V by n>>10.
// ---------------------------------------------------------------------------
__device__ __forceinline__ void mma16816(float* d, const uint32_t* a,
                                         uint32_t b0, uint32_t b1) {
    asm volatile(
        "mma.sync.aligned.m16n8k16.row.col.f32.bf16.bf16.f32 "
        "{%0,%1,%2,%3}, {%4,%5,%6,%7}, {%8,%9}, {%0,%1,%2,%3};"
        : "+f"(d[0]), "+f"(d[1]), "+f"(d[2]), "+f"(d[3])
        : "r"(a[0]), "r"(a[1]), "r"(a[2]), "r"(a[3]), "r"(b0), "r"(b1));
}

template <int OMODE>
__global__ __launch_bounds__(256)
void gemmH(float* __restrict__ Carg)
{
    // 2 stages x (A 128x32 + B 128x32) bf16, rows padded to 80B.
    __shared__ __align__(128) char smem[2 * 20480];

    const int tid    = threadIdx.x;
    const int lane   = tid & 31;
    const int wid    = tid >> 5;
    const int warp_m = wid & 3;        // 4 warps along M (32 rows each)
    const int warp_n = wid >> 2;       // 2 warps along N (64 cols each)
    const int bn     = blockIdx.x * 128;
    const int bm     = blockIdx.y * 128;
    const uint32_t sbase = smem_u32(smem);

    const __nv_bfloat16* AP[3] = {g_xhi, g_xhi, g_xlo};
    const __nv_bfloat16* BP[3] = {g_whi, g_wlo, g_whi};

    float acc[2][8][4];
#pragma unroll
    for (int i = 0; i < 2; i++)
#pragma unroll
        for (int j = 0; j < 8; j++)
#pragma unroll
            for (int t = 0; t < 4; t++) acc[i][j][t] = 0.f;

    auto issue = [&](int stage, int chunk) {
        const __nv_bfloat16* Ap = AP[chunk >> 5];
        const __nv_bfloat16* Bp = BP[chunk >> 5];
        const int k0 = (chunk & 31) * 32;
        const uint32_t sA = sbase + stage * 20480;
        const uint32_t sB = sA + 10240;
#pragma unroll
        for (int i = 0; i < 2; i++) {
            int idx = tid + i * 256;          // 0..511
            int r = idx >> 2, c = idx & 3;    // row 0..127, 16B seg 0..3
            const void* ga = Ap + (size_t)(bm + r) * 1024 + k0 + c * 8;
            asm volatile("cp.async.cg.shared.global [%0], [%1], 16;"
                         :: "r"(sA + r * 80 + c * 16), "l"(ga));
            const void* gb = Bp + (size_t)(bn + r) * 1024 + k0 + c * 8;
            asm volatile("cp.async.cg.shared.global [%0], [%1], 16;"
                         :: "r"(sB + r * 80 + c * 16), "l"(gb));
        }
        asm volatile("cp.async.commit_group;" ::: "memory");
    };

    issue(0, 0);

    for (int c = 0; c < 96; c++) {
        if (c + 1 < 96) {
            issue((c + 1) & 1, c + 1);
            asm volatile("cp.async.wait_group 1;" ::: "memory");
        } else {
            asm volatile("cp.async.wait_group 0;" ::: "memory");
        }
        __syncthreads();

        const uint32_t sA = sbase + (c & 1) * 20480;
        const uint32_t sB = sA + 10240;

        // A fragments: 2 m16 tiles x 2 k16 steps
        uint32_t a[2][2][4];
#pragma unroll
        for (int mt = 0; mt < 2; mt++)
#pragma unroll
            for (int ks = 0; ks < 2; ks++) {
                uint32_t ad = sA + (warp_m * 32 + mt * 16 + (lane & 15)) * 80
                            + ks * 32 + (lane >> 4) * 16;
                asm volatile("ldmatrix.sync.aligned.m8n8.x4.shared.b16 {%0,%1,%2,%3}, [%4];"
                    : "=r"(a[mt][ks][0]), "=r"(a[mt][ks][1]),
                      "=r"(a[mt][ks][2]), "=r"(a[mt][ks][3]) : "r"(ad));
            }
        // B fragments: 4 n16 groups x 2 k16 steps (each x4 = two n8 frags)
        uint32_t b[4][2][4];
#pragma unroll
        for (int ng = 0; ng < 4; ng++)
#pragma unroll
            for (int ks = 0; ks < 2; ks++) {
                uint32_t bd = sB + (warp_n * 64 + ng * 16 + ((lane >> 4) << 3) + (lane & 7)) * 80
                            + ks * 32 + ((lane >> 3) & 1) * 16;
                asm volatile("ldmatrix.sync.aligned.m8n8.x4.shared.b16 {%0,%1,%2,%3}, [%4];"
                    : "=r"(b[ng][ks][0]), "=r"(b[ng][ks][1]),
                      "=r"(b[ng][ks][2]), "=r"(b[ng][ks][3]) : "r"(bd));
            }
#pragma unroll
        for (int mt = 0; mt < 2; mt++)
#pragma unroll
            for (int ng = 0; ng < 4; ng++)
#pragma unroll
                for (int ks = 0; ks < 2; ks++) {
                    mma16816(acc[mt][ng * 2 + 0], a[mt][ks], b[ng][ks][0], b[ng][ks][1]);
                    mma16816(acc[mt][ng * 2 + 1], a[mt][ks], b[ng][ks][2], b[ng][ks][3]);
                }
        __syncthreads();
    }

    // Epilogue
    const int tq = lane >> 2;          // row within 8
    const int tr = (lane & 3) * 2;     // col pair
    const int which = bn >> 10;        // OMODE1: 0=Q 1=K 2=V
    const int head  = ((bn & 1023) >> 6) + warp_n;
    float* dst = (which == 0) ? g_Q : (which == 1) ? g_K : g_V;

#pragma unroll
    for (int mt = 0; mt < 2; mt++)
#pragma unroll
        for (int half = 0; half < 2; half++) {
            int row = bm + warp_m * 32 + mt * 16 + half * 8 + tq;
            float* p;
            if (OMODE == 0) {
                p = Carg + (size_t)row * 1024 + bn + warp_n * 64 + tr;
            } else {
                int bb = row >> 11, ss = row & 2047;
                p = dst + (((size_t)(bb * kH + head) * kS + ss) << 6) + tr;
            }
#pragma unroll
            for (int n8 = 0; n8 < 8; n8++) {
                float2 v = half ? make_float2(acc[mt][n8][2], acc[mt][n8][3])
                                : make_float2(acc[mt][n8][0], acc[mt][n8][1]);
                *(float2*)(p + n8 * 8) = v;
            }
        }
}

// ---------------------------------------------------------------------------
// Causal flash attention, fp32 (unchanged from passing round-5 kernel)
// ---------------------------------------------------------------------------
__global__ __launch_bounds__(128)
void flash_attn()
{
    __shared__ __align__(16) float4 Ks[64][16];
    __shared__ __align__(16) float4 Vs[64][16];

    const int tid  = threadIdx.x;
    const int qblk = blockIdx.x;
    const int bh   = blockIdx.y;
    const int b    = bh >> 4;
    const int h    = bh & 15;
    const int qi   = qblk * 128 + tid;

    const float* Qbase = g_Q + (size_t)bh * kS * 64;
    const float* Kbase = g_K + (size_t)bh * kS * 64;
    const float* Vbase = g_V + (size_t)bh * kS * 64;

    float q[64];
#pragma unroll
    for (int i = 0; i < 8; i++) {
        int e = tid + i * 128;
        int r = e >> 4, c = e & 15;
        Ks[r][c] = ((const float4*)(Qbase + (size_t)(qblk * 128 + r) * 64))[c];
        Vs[r][c] = ((const float4*)(Qbase + (size_t)(qblk * 128 + 64 + r) * 64))[c];
    }
    __syncthreads();
#pragma unroll
    for (int c = 0; c < 16; c++) {
        float4 v = (tid < 64) ? Ks[tid][c] : Vs[tid - 64][c];
        q[c * 4 + 0] = v.x; q[c * 4 + 1] = v.y;
        q[c * 4 + 2] = v.z; q[c * 4 + 3] = v.w;
    }
    __syncthreads();

    float o[64];
#pragma unroll
    for (int d = 0; d < 64; d++) o[d] = 0.f;
    float m = -1e30f, l = 0.f;

    const int ktiles = qblk * 2 + 2;
    for (int kt = 0; kt < ktiles; kt++) {
#pragma unroll
        for (int i = 0; i < 8; i++) {
            int e = tid + i * 128;
            int r = e >> 4, c = e & 15;
            Ks[r][c] = ((const float4*)(Kbase + (size_t)(kt * 64 + r) * 64))[c];
            Vs[r][c] = ((const float4*)(Vbase + (size_t)(kt * 64 + r) * 64))[c];
        }
        __syncthreads();

        const int kbase = kt * 64;
#pragma unroll 1
        for (int j = 0; j < 64; j++) {
            int kg = kbase + j;
            float s = 0.f;
#pragma unroll
            for (int c = 0; c < 16; c++) {
                float4 kv = Ks[j][c];
                s += q[c * 4 + 0] * kv.x + q[c * 4 + 1] * kv.y
                   + q[c * 4 + 2] * kv.z + q[c * 4 + 3] * kv.w;
            }
            s *= 0.125f;
            if (kg > qi) s = -1e30f;
            if (s > m) {
                float corr = __expf(m - s);
                m = s;
                l *= corr;
#pragma unroll
                for (int d = 0; d < 64; d++) o[d] *= corr;
            }
            float p = __expf(s - m);
            l += p;
#pragma unroll
            for (int c = 0; c < 16; c++) {
                float4 vv = Vs[j][c];
                o[c * 4 + 0] += p * vv.x; o[c * 4 + 1] += p * vv.y;
                o[c * 4 + 2] += p * vv.z; o[c * 4 + 3] += p * vv.w;
            }
        }
        __syncthreads();
    }

    const float inv = 1.f / l;
    float* out = g_CTX + ((size_t)(b * kS + qi) * kH + h) * 64;
#pragma unroll
    for (int c = 0; c < 16; c++) {
        float4 v;
        v.x = o[c * 4 + 0] * inv; v.y = o[c * 4 + 1] * inv;
        v.z = o[c * 4 + 2] * inv; v.w = o[c * 4 + 3] * inv;
        ((float4*)out)[c] = v;
    }
}

// ---------------------------------------------------------------------------
extern "C" void kernel_launch(void* const* d_in, const int* in_sizes, int n_in,
                              void* d_out, int out_size)
{
    const float* x  = (const float*)d_in[0];   // [B,S,D]
    const float* Wq = (const float*)d_in[1];   // [H,D,64]
    const float* Wk = (const float*)d_in[2];
    const float* Wv = (const float*)d_in[3];
    const float* Wo = (const float*)d_in[4];   // [1024,1024]
    float* out = (float*)d_out;

    // x -> bf16 hi/lo split
    cvt_split<0><<<8192, 256>>>(x);

    // Fused QKV weights -> [3072][1024] K-major split
    cvt_w<1><<<4096, 256>>>(Wq, 0);
    cvt_w<1><<<4096, 256>>>(Wk, 1024);
    cvt_w<1><<<4096, 256>>>(Wv, 2048);

    // Fused QKV projection (scatter into g_Q/g_K/g_V)
    gemmH<1><<<dim3(24, 64), 256>>>(nullptr);

    // Causal attention -> g_CTX
    flash_attn<<<dim3(kS / 128, kB * kH), 128>>>();

    // ctx split + output projection
    cvt_split<1><<<8192, 256>>>(nullptr);
    cvt_w<0><<<4096, 256>>>(Wo, 0);
    gemmH<0><<<dim3(8, 64), 256>>>(out);
}

// round 11
// speedup vs baseline: 3.2117x; 1.8597x over previous
#include <cuda_runtime.h>
#include <cuda_bf16.h>
#include <math.h>
#include <stdint.h>

// Problem constants
constexpr int kB  = 4;
constexpr int kS  = 2048;
constexpr int kD  = 1024;
constexpr int kH  = 16;

// ---------------------------------------------------------------------------
// Scratch (device globals — no allocation allowed)
// ---------------------------------------------------------------------------
__device__ float g_Q[kB * kH * kS * 64];    // [B,H,S,64] fp32
__device__ float g_K[kB * kH * kS * 64];
__device__ float g_V[kB * kH * kS * 64];
__device__ float g_CTX[kB * kS * kH * 64];  // [B,S,H*64] fp32 == [8192,1024]

__device__ __nv_bfloat16 g_xhi[kB * kS * kD];   // A split (x or ctx) [8192,1024]
__device__ __nv_bfloat16 g_xlo[kB * kS * kD];
__device__ __nv_bfloat16 g_whi[3 * kD * kD];    // B split, [N<=3072][K=1024] K-major
__device__ __nv_bfloat16 g_wlo[3 * kD * kD];

// Attention operands, bf16 hi/lo
__device__ __nv_bfloat16 g_Qhi[kB * kH * kS * 64];   // [B,H,S,64]
__device__ __nv_bfloat16 g_Qlo[kB * kH * kS * 64];
__device__ __nv_bfloat16 g_Khi[kB * kH * kS * 64];
__device__ __nv_bfloat16 g_Klo[kB * kH * kS * 64];
__device__ __nv_bfloat16 g_VThi[kB * kH * 64 * kS];  // [B,H,64(d),S] transposed
__device__ __nv_bfloat16 g_VTlo[kB * kH * 64 * kS];

__device__ __forceinline__ uint32_t smem_u32(const void* p) {
    uint32_t a;
    asm("{ .reg .u64 t; cvta.to.shared.u64 t, %1; cvt.u32.u64 %0, t; }" : "=r"(a) : "l"(p));
    return a;
}
__device__ __forceinline__ uint32_t packbf(float a, float b) {
    __nv_bfloat162 t = __floats2bfloat162_rn(a, b);
    return *(uint32_t*)&t;
}

// ---------------------------------------------------------------------------
// Conversion kernels
// ---------------------------------------------------------------------------
template <int SRC>  // 0 = arg, 1 = g_CTX
__global__ __launch_bounds__(256)
void cvt_split(const float* __restrict__ src_arg)
{
    const float* src = (SRC == 1) ? g_CTX : src_arg;
    int i = blockIdx.x * 256 + threadIdx.x;
    float4 v = ((const float4*)src)[i];
    __nv_bfloat16 h0 = __float2bfloat16(v.x), h1 = __float2bfloat16(v.y);
    __nv_bfloat16 h2 = __float2bfloat16(v.z), h3 = __float2bfloat16(v.w);
    __nv_bfloat16 l0 = __float2bfloat16(v.x - __bfloat162float(h0));
    __nv_bfloat16 l1 = __float2bfloat16(v.y - __bfloat162float(h1));
    __nv_bfloat16 l2 = __float2bfloat16(v.z - __bfloat162float(h2));
    __nv_bfloat16 l3 = __float2bfloat16(v.w - __bfloat162float(h3));
    ((__nv_bfloat162*)g_xhi)[i * 2 + 0] = __nv_bfloat162(h0, h1);
    ((__nv_bfloat162*)g_xhi)[i * 2 + 1] = __nv_bfloat162(h2, h3);
    ((__nv_bfloat162*)g_xlo)[i * 2 + 0] = __nv_bfloat162(l0, l1);
    ((__nv_bfloat162*)g_xlo)[i * 2 + 1] = __nv_bfloat162(l2, l3);
}

template <int HEAD>
__global__ __launch_bounds__(256)
void cvt_w(const float* __restrict__ W, int n_off)
{
    int idx = blockIdx.x * 256 + threadIdx.x;
    float v = W[idx];
    int n, k;
    if (HEAD) { int dk = idx & 63, kk = (idx >> 6) & 1023, h = idx >> 16;
                n = n_off + h * 64 + dk; k = kk; }
    else      { n = n_off + (idx & 1023); k = idx >> 10; }
    __nv_bfloat16 hi = __float2bfloat16(v);
    __nv_bfloat16 lo = __float2bfloat16(v - __bfloat162float(hi));
    g_whi[(size_t)n * 1024 + k] = hi;
    g_wlo[(size_t)n * 1024 + k] = lo;
}

// Q/K fp32 -> bf16 hi/lo (elementwise, same layout)
template <int SEL>  // 0: Q, 1: K
__global__ __launch_bounds__(256)
void qk_split()
{
    const float* src = SEL ? g_K : g_Q;
    __nv_bfloat16* dh = SEL ? g_Khi : g_Qhi;
    __nv_bfloat16* dl = SEL ? g_Klo : g_Qlo;
    int i = blockIdx.x * 256 + threadIdx.x;       // float4 index
    float4 v = ((const float4*)src)[i];
    __nv_bfloat16 h0 = __float2bfloat16(v.x), h1 = __float2bfloat16(v.y);
    __nv_bfloat16 h2 = __float2bfloat16(v.z), h3 = __float2bfloat16(v.w);
    __nv_bfloat16 l0 = __float2bfloat16(v.x - __bfloat162float(h0));
    __nv_bfloat16 l1 = __float2bfloat16(v.y - __bfloat162float(h1));
    __nv_bfloat16 l2 = __float2bfloat16(v.z - __bfloat162float(h2));
    __nv_bfloat16 l3 = __float2bfloat16(v.w - __bfloat162float(h3));
    ((__nv_bfloat162*)dh)[i * 2 + 0] = __nv_bfloat162(h0, h1);
    ((__nv_bfloat162*)dh)[i * 2 + 1] = __nv_bfloat162(h2, h3);
    ((__nv_bfloat162*)dl)[i * 2 + 0] = __nv_bfloat162(l0, l1);
    ((__nv_bfloat162*)dl)[i * 2 + 1] = __nv_bfloat162(l2, l3);
}

// V fp32 [B,H,S,64] -> VT bf16 hi/lo [B,H,64,S], tiled 64x64 transpose
__global__ __launch_bounds__(256)
void vt_split()
{
    __shared__ float tile[64][65];
    const int s0 = blockIdx.x * 64;
    const int bh = blockIdx.y;
    const int tid = threadIdx.x;
    const float* src = g_V + (size_t)bh * kS * 64;
#pragma unroll
    for (int i = 0; i < 16; i++) {
        int idx = tid + i * 256;          // 0..4095
        int r = idx >> 6, c = idx & 63;
        tile[r][c] = src[(size_t)(s0 + r) * 64 + c];
    }
    __syncthreads();
#pragma unroll
    for (int i = 0; i < 16; i++) {
        int idx = tid + i * 256;
        int d = idx >> 6, ss = idx & 63;
        float v = tile[ss][d];
        __nv_bfloat16 hi = __float2bfloat16(v);
        __nv_bfloat16 lo = __float2bfloat16(v - __bfloat162float(hi));
        size_t o = ((size_t)bh * 64 + d) * kS + s0 + ss;
        g_VThi[o] = hi;
        g_VTlo[o] = lo;
    }
}

// ---------------------------------------------------------------------------
// HMMA helpers
// ---------------------------------------------------------------------------
__device__ __forceinline__ void mma16816(float* d, const uint32_t* a,
                                         uint32_t b0, uint32_t b1) {
    asm volatile(
        "mma.sync.aligned.m16n8k16.row.col.f32.bf16.bf16.f32 "
        "{%0,%1,%2,%3}, {%4,%5,%6,%7}, {%8,%9}, {%0,%1,%2,%3};"
        : "+f"(d[0]), "+f"(d[1]), "+f"(d[2]), "+f"(d[3])
        : "r"(a[0]), "r"(a[1]), "r"(a[2]), "r"(a[3]), "r"(b0), "r"(b1));
}
#define LDSM_X4(r, addr) \
    asm volatile("ldmatrix.sync.aligned.m8n8.x4.shared.b16 {%0,%1,%2,%3}, [%4];" \
        : "=r"((r)[0]), "=r"((r)[1]), "=r"((r)[2]), "=r"((r)[3]) : "r"(addr))

// ---------------------------------------------------------------------------
// HMMA split-bf16 GEMM (unchanged from passing round-8 kernel)
// ---------------------------------------------------------------------------
template <int OMODE>
__global__ __launch_bounds__(256)
void gemmH(float* __restrict__ Carg)
{
    __shared__ __align__(128) char smem[2 * 20480];

    const int tid    = threadIdx.x;
    const int lane   = tid & 31;
    const int wid    = tid >> 5;
    const int warp_m = wid & 3;
    const int warp_n = wid >> 2;
    const int bn     = blockIdx.x * 128;
    const int bm     = blockIdx.y * 128;
    const uint32_t sbase = smem_u32(smem);

    const __nv_bfloat16* AP[3] = {g_xhi, g_xhi, g_xlo};
    const __nv_bfloat16* BP[3] = {g_whi, g_wlo, g_whi};

    float acc[2][8][4];
#pragma unroll
    for (int i = 0; i < 2; i++)
#pragma unroll
        for (int j = 0; j < 8; j++)
#pragma unroll
            for (int t = 0; t < 4; t++) acc[i][j][t] = 0.f;

    auto issue = [&](int stage, int chunk) {
        const __nv_bfloat16* Ap = AP[chunk >> 5];
        const __nv_bfloat16* Bp = BP[chunk >> 5];
        const int k0 = (chunk & 31) * 32;
        const uint32_t sA = sbase + stage * 20480;
        const uint32_t sB = sA + 10240;
#pragma unroll
        for (int i = 0; i < 2; i++) {
            int idx = tid + i * 256;
            int r = idx >> 2, c = idx & 3;
            const void* ga = Ap + (size_t)(bm + r) * 1024 + k0 + c * 8;
            asm volatile("cp.async.cg.shared.global [%0], [%1], 16;"
                         :: "r"(sA + r * 80 + c * 16), "l"(ga));
            const void* gb = Bp + (size_t)(bn + r) * 1024 + k0 + c * 8;
            asm volatile("cp.async.cg.shared.global [%0], [%1], 16;"
                         :: "r"(sB + r * 80 + c * 16), "l"(gb));
        }
        asm volatile("cp.async.commit_group;" ::: "memory");
    };

    issue(0, 0);

    for (int c = 0; c < 96; c++) {
        if (c + 1 < 96) {
            issue((c + 1) & 1, c + 1);
            asm volatile("cp.async.wait_group 1;" ::: "memory");
        } else {
            asm volatile("cp.async.wait_group 0;" ::: "memory");
        }
        __syncthreads();

        const uint32_t sA = sbase + (c & 1) * 20480;
        const uint32_t sB = sA + 10240;

        uint32_t a[2][2][4];
#pragma unroll
        for (int mt = 0; mt < 2; mt++)
#pragma unroll
            for (int ks = 0; ks < 2; ks++) {
                uint32_t ad = sA + (warp_m * 32 + mt * 16 + (lane & 15)) * 80
                            + ks * 32 + (lane >> 4) * 16;
                LDSM_X4(a[mt][ks], ad);
            }
        uint32_t b[4][2][4];
#pragma unroll
        for (int ng = 0; ng < 4; ng++)
#pragma unroll
            for (int ks = 0; ks < 2; ks++) {
                uint32_t bd = sB + (warp_n * 64 + ng * 16 + ((lane >> 4) << 3) + (lane & 7)) * 80
                            + ks * 32 + ((lane >> 3) & 1) * 16;
                LDSM_X4(b[ng][ks], bd);
            }
#pragma unroll
        for (int mt = 0; mt < 2; mt++)
#pragma unroll
            for (int ng = 0; ng < 4; ng++)
#pragma unroll
                for (int ks = 0; ks < 2; ks++) {
                    mma16816(acc[mt][ng * 2 + 0], a[mt][ks], b[ng][ks][0], b[ng][ks][1]);
                    mma16816(acc[mt][ng * 2 + 1], a[mt][ks], b[ng][ks][2], b[ng][ks][3]);
                }
        __syncthreads();
    }

    const int tq = lane >> 2;
    const int tr = (lane & 3) * 2;
    const int which = bn >> 10;
    const int head  = ((bn & 1023) >> 6) + warp_n;
    float* dst = (which == 0) ? g_Q : (which == 1) ? g_K : g_V;

#pragma unroll
    for (int mt = 0; mt < 2; mt++)
#pragma unroll
        for (int half = 0; half < 2; half++) {
            int row = bm + warp_m * 32 + mt * 16 + half * 8 + tq;
            float* p;
            if (OMODE == 0) {
                p = Carg + (size_t)row * 1024 + bn + warp_n * 64 + tr;
            } else {
                int bb = row >> 11, ss = row & 2047;
                p = dst + (((size_t)(bb * kH + head) * kS + ss) << 6) + tr;
            }
#pragma unroll
            for (int n8 = 0; n8 < 8; n8++) {
                float2 v = half ? make_float2(acc[mt][n8][2], acc[mt][n8][3])
                                : make_float2(acc[mt][n8][0], acc[mt][n8][1]);
                *(float2*)(p + n8 * 8) = v;
            }
        }
}

// ---------------------------------------------------------------------------
// HMMA causal flash attention, split-bf16 (fp32-accurate)
// grid (S/128, B*H), 256 threads, 8 warps x 16 q-rows.
// K tiles of 64 keys; smem: Khi|Klo|VThi|VTlo, 64 rows x 144B each.
// ---------------------------------------------------------------------------
__global__ __launch_bounds__(256)
void flash_hmma()
{
    __shared__ __align__(128) char sm[4 * 9216];   // 36864

    const int tid  = threadIdx.x;
    const int lane = tid & 31;
    const int wid  = tid >> 5;
    const int qblk = blockIdx.x;
    const int bh   = blockIdx.y;
    const int b    = bh >> 4;
    const int h    = bh & 15;
    const int qrow0 = qblk * 128 + wid * 16;
    const uint32_t sb = smem_u32(sm);

    // ---- Stage Q (128 rows x 64) hi/lo and load fragments ----
    {
        const __nv_bfloat16* Qh = g_Qhi + ((size_t)bh * kS + qblk * 128) * 64;
        const __nv_bfloat16* Ql = g_Qlo + ((size_t)bh * kS + qblk * 128) * 64;
#pragma unroll
        for (int i = 0; i < 4; i++) {
            int idx = tid + i * 256;           // 0..1023
            int r = idx >> 3, c = idx & 7;
            *(uint4*)(sm + r * 144 + c * 16)         = *(const uint4*)(Qh + (size_t)r * 64 + c * 8);
            *(uint4*)(sm + 18432 + r * 144 + c * 16) = *(const uint4*)(Ql + (size_t)r * 64 + c * 8);
        }
    }
    __syncthreads();

    uint32_t qh[4][4], ql[4][4];
#pragma unroll
    for (int ks = 0; ks < 4; ks++) {
        uint32_t ad = sb + (wid * 16 + (lane & 15)) * 144 + ks * 32 + (lane >> 4) * 16;
        LDSM_X4(qh[ks], ad);
        LDSM_X4(ql[ks], ad + 18432);
    }

    float m0 = -1e30f, m1 = -1e30f, l0 = 0.f, l1 = 0.f;
    float ctx[8][4];
#pragma unroll
    for (int j = 0; j < 8; j++)
#pragma unroll
        for (int t = 0; t < 4; t++) ctx[j][t] = 0.f;

    const int ktiles = 2 * qblk + 2;
    const int r0g = qrow0 + (lane >> 2);       // this thread's first row
    const int r1g = r0g + 8;

    for (int kt = 0; kt < ktiles; kt++) {
        __syncthreads();                        // protect smem reuse
        // ---- Load K hi/lo + VT hi/lo tiles ----
        {
            const __nv_bfloat16* Kh = g_Khi + ((size_t)bh * kS + kt * 64) * 64;
            const __nv_bfloat16* Kl = g_Klo + ((size_t)bh * kS + kt * 64) * 64;
            const __nv_bfloat16* Vh = g_VThi + (size_t)bh * 64 * kS + kt * 64;
            const __nv_bfloat16* Vl = g_VTlo + (size_t)bh * 64 * kS + kt * 64;
#pragma unroll
            for (int i = 0; i < 8; i++) {
                int idx = tid + i * 256;        // 0..2047
                int buf = idx >> 9, rem = idx & 511;
                int r = rem >> 3, c = rem & 7;
                const uint4* src;
                if      (buf == 0) src = (const uint4*)(Kh + (size_t)r * 64 + c * 8);
                else if (buf == 1) src = (const uint4*)(Kl + (size_t)r * 64 + c * 8);
                else if (buf == 2) src = (const uint4*)(Vh + (size_t)r * kS + c * 8);
                else               src = (const uint4*)(Vl + (size_t)r * kS + c * 8);
                *(uint4*)(sm + buf * 9216 + r * 144 + c * 16) = *src;
            }
        }
        __syncthreads();

        if (qrow0 + 15 < kt * 64) continue;     // fully masked for this warp

        // ---- S = Q K^T (3-pass split) ----
        float sf[8][4];
#pragma unroll
        for (int j = 0; j < 8; j++)
#pragma unroll
            for (int t = 0; t < 4; t++) sf[j][t] = 0.f;

#pragma unroll
        for (int ks = 0; ks < 4; ks++) {
#pragma unroll
            for (int ng = 0; ng < 4; ng++) {
                uint32_t bd = sb + (ng * 16 + ((lane >> 4) << 3) + (lane & 7)) * 144
                            + ks * 32 + ((lane >> 3) & 1) * 16;
                uint32_t bhif[4], blof[4];
                LDSM_X4(bhif, bd);
                LDSM_X4(blof, bd + 9216);
                mma16816(sf[ng * 2 + 0], qh[ks], bhif[0], bhif[1]);
                mma16816(sf[ng * 2 + 1], qh[ks], bhif[2], bhif[3]);
                mma16816(sf[ng * 2 + 0], qh[ks], blof[0], blof[1]);
                mma16816(sf[ng * 2 + 1], qh[ks], blof[2], blof[3]);
                mma16816(sf[ng * 2 + 0], ql[ks], bhif[0], bhif[1]);
                mma16816(sf[ng * 2 + 1], ql[ks], bhif[2], bhif[3]);
            }
        }

        // ---- scale + causal mask ----
#pragma unroll
        for (int j = 0; j < 8; j++) {
            int kg = kt * 64 + j * 8 + 2 * (lane & 3);
            sf[j][0] = (kg     <= r0g) ? sf[j][0] * 0.125f : -1e30f;
            sf[j][1] = (kg + 1 <= r0g) ? sf[j][1] * 0.125f : -1e30f;
            sf[j][2] = (kg     <= r1g) ? sf[j][2] * 0.125f : -1e30f;
            sf[j][3] = (kg + 1 <= r1g) ? sf[j][3] * 0.125f : -1e30f;
        }

        // ---- online softmax ----
        float rm0 = -1e30f, rm1 = -1e30f;
#pragma unroll
        for (int j = 0; j < 8; j++) {
            rm0 = fmaxf(rm0, fmaxf(sf[j][0], sf[j][1]));
            rm1 = fmaxf(rm1, fmaxf(sf[j][2], sf[j][3]));
        }
        rm0 = fmaxf(rm0, __shfl_xor_sync(0xffffffff, rm0, 1));
        rm0 = fmaxf(rm0, __shfl_xor_sync(0xffffffff, rm0, 2));
        rm1 = fmaxf(rm1, __shfl_xor_sync(0xffffffff, rm1, 1));
        rm1 = fmaxf(rm1, __shfl_xor_sync(0xffffffff, rm1, 2));

        float m0n = fmaxf(m0, rm0), m1n = fmaxf(m1, rm1);
        float sc0 = __expf(m0 - m0n), sc1 = __expf(m1 - m1n);
        m0 = m0n; m1 = m1n;

        float rs0 = 0.f, rs1 = 0.f;
#pragma unroll
        for (int j = 0; j < 8; j++) {
            sf[j][0] = __expf(sf[j][0] - m0);
            sf[j][1] = __expf(sf[j][1] - m0);
            sf[j][2] = __expf(sf[j][2] - m1);
            sf[j][3] = __expf(sf[j][3] - m1);
            rs0 += sf[j][0] + sf[j][1];
            rs1 += sf[j][2] + sf[j][3];
        }
        rs0 += __shfl_xor_sync(0xffffffff, rs0, 1);
        rs0 += __shfl_xor_sync(0xffffffff, rs0, 2);
        rs1 += __shfl_xor_sync(0xffffffff, rs1, 1);
        rs1 += __shfl_xor_sync(0xffffffff, rs1, 2);
        l0 = l0 * sc0 + rs0;
        l1 = l1 * sc1 + rs1;
#pragma unroll
        for (int j = 0; j < 8; j++) {
            ctx[j][0] *= sc0; ctx[j][1] *= sc0;
            ctx[j][2] *= sc1; ctx[j][3] *= sc1;
        }

        // ---- ctx += P V (3-pass split) ----
#pragma unroll
        for (int ks2 = 0; ks2 < 4; ks2++) {
            const int j0 = 2 * ks2, j1 = 2 * ks2 + 1;
            uint32_t ahi[4], alo[4];
            ahi[0] = packbf(sf[j0][0], sf[j0][1]);
            ahi[1] = packbf(sf[j0][2], sf[j0][3]);
            ahi[2] = packbf(sf[j1][0], sf[j1][1]);
            ahi[3] = packbf(sf[j1][2], sf[j1][3]);
            {
                float a0 = sf[j0][0] - __bfloat162float(__float2bfloat16(sf[j0][0]));
                float a1 = sf[j0][1] - __bfloat162float(__float2bfloat16(sf[j0][1]));
                float a2 = sf[j0][2] - __bfloat162float(__float2bfloat16(sf[j0][2]));
                float a3 = sf[j0][3] - __bfloat162float(__float2bfloat16(sf[j0][3]));
                float a4 = sf[j1][0] - __bfloat162float(__float2bfloat16(sf[j1][0]));
                float a5 = sf[j1][1] - __bfloat162float(__float2bfloat16(sf[j1][1]));
                float a6 = sf[j1][2] - __bfloat162float(__float2bfloat16(sf[j1][2]));
                float a7 = sf[j1][3] - __bfloat162float(__float2bfloat16(sf[j1][3]));
                alo[0] = packbf(a0, a1); alo[1] = packbf(a2, a3);
                alo[2] = packbf(a4, a5); alo[3] = packbf(a6, a7);
            }
#pragma unroll
            for (int ng = 0; ng < 4; ng++) {
                uint32_t vd = sb + 18432 + (ng * 16 + ((lane >> 4) << 3) + (lane & 7)) * 144
                            + ks2 * 32 + ((lane >> 3) & 1) * 16;
                uint32_t vhif[4], vlof[4];
                LDSM_X4(vhif, vd);
                LDSM_X4(vlof, vd + 9216);
                mma16816(ctx[ng * 2 + 0], ahi, vhif[0], vhif[1]);
                mma16816(ctx[ng * 2 + 1], ahi, vhif[2], vhif[3]);
                mma16816(ctx[ng * 2 + 0], ahi, vlof[0], vlof[1]);
                mma16816(ctx[ng * 2 + 1], ahi, vlof[2], vlof[3]);
                mma16816(ctx[ng * 2 + 0], alo, vhif[0], vhif[1]);
                mma16816(ctx[ng * 2 + 1], alo, vhif[2], vhif[3]);
            }
        }
    }

    // ---- epilogue: normalize + write ctx [B,S,H*64] ----
    const float inv0 = 1.f / l0, inv1 = 1.f / l1;
#pragma unroll
    for (int j = 0; j < 8; j++) {
        int d = j * 8 + 2 * (lane & 3);
        float* p0 = g_CTX + ((size_t)(b * kS + r0g)) * 1024 + h * 64 + d;
        float* p1 = g_CTX + ((size_t)(b * kS + r1g)) * 1024 + h * 64 + d;
        *(float2*)p0 = make_float2(ctx[j][0] * inv0, ctx[j][1] * inv0);
        *(float2*)p1 = make_float2(ctx[j][2] * inv1, ctx[j][3] * inv1);
    }
}

// ---------------------------------------------------------------------------
extern "C" void kernel_launch(void* const* d_in, const int* in_sizes, int n_in,
                              void* d_out, int out_size)
{
    const float* x  = (const float*)d_in[0];   // [B,S,D]
    const float* Wq = (const float*)d_in[1];   // [H,D,64]
    const float* Wk = (const float*)d_in[2];
    const float* Wv = (const float*)d_in[3];
    const float* Wo = (const float*)d_in[4];   // [1024,1024]
    float* out = (float*)d_out;

    // x -> bf16 hi/lo split
    cvt_split<0><<<8192, 256>>>(x);

    // Fused QKV weights -> [3072][1024] K-major split
    cvt_w<1><<<4096, 256>>>(Wq, 0);
    cvt_w<1><<<4096, 256>>>(Wk, 1024);
    cvt_w<1><<<4096, 256>>>(Wv, 2048);

    // Fused QKV projection (scatter into g_Q/g_K/g_V fp32)
    gemmH<1><<<dim3(24, 64), 256>>>(nullptr);

    // Q/K -> bf16 hi/lo; V -> transposed bf16 hi/lo
    qk_split<0><<<8192, 256>>>();
    qk_split<1><<<8192, 256>>>();
    vt_split<<<dim3(kS / 64, kB * kH), 256>>>();

    // Causal attention on tensor cores -> g_CTX
    flash_hmma<<<dim3(kS / 128, kB * kH), 256>>>();

    // ctx split + output projection
    cvt_split<1><<<8192, 256>>>(nullptr);
    cvt_w<0><<<4096, 256>>>(Wo, 0);
    gemmH<0><<<dim3(8, 64), 256>>>(out);
}

// round 15
// speedup vs baseline: 3.4093x; 1.0615x over previous
#include <cuda_runtime.h>
#include <cuda_bf16.h>
#include <math.h>
#include <stdint.h>

// Problem constants
constexpr int kB  = 4;
constexpr int kS  = 2048;
constexpr int kD  = 1024;
constexpr int kH  = 16;

// ---------------------------------------------------------------------------
// Scratch (device globals — no allocation allowed)
// ---------------------------------------------------------------------------
__device__ float g_V[kB * kH * kS * 64];        // [B,H,S,64] fp32 (for transpose)

__device__ __nv_bfloat16 g_xhi[kB * kS * kD];   // A split (x, then ctx) [8192,1024]
__device__ __nv_bfloat16 g_xlo[kB * kS * kD];
__device__ __nv_bfloat16 g_whi[3 * kD * kD];    // B split, [N<=3072][K=1024] K-major
__device__ __nv_bfloat16 g_wlo[3 * kD * kD];

// Attention operands, bf16 hi/lo
__device__ __nv_bfloat16 g_Qhi[kB * kH * kS * 64];   // [B,H,S,64]
__device__ __nv_bfloat16 g_Qlo[kB * kH * kS * 64];
__device__ __nv_bfloat16 g_Khi[kB * kH * kS * 64];
__device__ __nv_bfloat16 g_Klo[kB * kH * kS * 64];
__device__ __nv_bfloat16 g_VThi[kB * kH * 64 * kS];  // [B,H,64(d),S]
__device__ __nv_bfloat16 g_VTlo[kB * kH * 64 * kS];

__device__ __forceinline__ uint32_t smem_u32(const void* p) {
    uint32_t a;
    asm("{ .reg .u64 t; cvta.to.shared.u64 t, %1; cvt.u32.u64 %0, t; }" : "=r"(a) : "l"(p));
    return a;
}
__device__ __forceinline__ uint32_t packbf(float a, float b) {
    __nv_bfloat162 t = __floats2bfloat162_rn(a, b);
    return *(uint32_t*)&t;
}

// ---------------------------------------------------------------------------
// Conversion kernels
// ---------------------------------------------------------------------------
// x -> bf16 hi/lo split (row-major [8192,1024])
__global__ __launch_bounds__(256)
void cvt_split(const float* __restrict__ src)
{
    int i = blockIdx.x * 256 + threadIdx.x;       // float4 index
    float4 v = ((const float4*)src)[i];
    __nv_bfloat16 h0 = __float2bfloat16(v.x), h1 = __float2bfloat16(v.y);
    __nv_bfloat16 h2 = __float2bfloat16(v.z), h3 = __float2bfloat16(v.w);
    __nv_bfloat16 l0 = __float2bfloat16(v.x - __bfloat162float(h0));
    __nv_bfloat16 l1 = __float2bfloat16(v.y - __bfloat162float(h1));
    __nv_bfloat16 l2 = __float2bfloat16(v.z - __bfloat162float(h2));
    __nv_bfloat16 l3 = __float2bfloat16(v.w - __bfloat162float(h3));
    ((__nv_bfloat162*)g_xhi)[i * 2 + 0] = __nv_bfloat162(h0, h1);
    ((__nv_bfloat162*)g_xhi)[i * 2 + 1] = __nv_bfloat162(h2, h3);
    ((__nv_bfloat162*)g_xlo)[i * 2 + 0] = __nv_bfloat162(l0, l1);
    ((__nv_bfloat162*)g_xlo)[i * 2 + 1] = __nv_bfloat162(l2, l3);
}

// Weights -> g_whi/g_wlo [n][k] K-major, smem-tiled so writes are contiguous.
// HEAD 1: W [H,D,64]:   n = n_off + h*64 + dk, k = d.   grid (kt=16, h=16)
// HEAD 0: W [1024,1024]: n = n_off + col,      k = row.  grid (kt=16, nt=16)
template <int HEAD>
__global__ __launch_bounds__(256)
void cvt_wT(const float* __restrict__ W, int n_off)
{
    __shared__ float tile[64][65];
    const int kt = blockIdx.x;
    const int hz = blockIdx.y;
    const int tid = threadIdx.x;
#pragma unroll
    for (int i = 0; i < 16; i++) {
        int e = tid + i * 256;
        int r = e >> 6, c = e & 63;           // r: k-in-tile, c: n-in-tile
        float v;
        if (HEAD) v = W[((size_t)hz * 1024 + kt * 64 + r) * 64 + c];
        else      v = W[(size_t)(kt * 64 + r) * 1024 + hz * 64 + c];
        tile[r][c] = v;
    }
    __syncthreads();
#pragma unroll
    for (int i = 0; i < 16; i++) {
        int e = tid + i * 256;
        int rr = e >> 6, cc = e & 63;         // rr: n-in-tile, cc: k-in-tile
        float v = tile[cc][rr];
        __nv_bfloat16 hi = __float2bfloat16(v);
        __nv_bfloat16 lo = __float2bfloat16(v - __bfloat162float(hi));
        int n = n_off + hz * 64 + rr;
        int k = kt * 64 + cc;
        g_whi[(size_t)n * 1024 + k] = hi;
        g_wlo[(size_t)n * 1024 + k] = lo;
    }
}

// V fp32 [B,H,S,64] -> VT bf16 hi/lo [B,H,64,S]
__global__ __launch_bounds__(256)
void vt_split()
{
    __shared__ float tile[64][65];
    const int s0 = blockIdx.x * 64;
    const int bh = blockIdx.y;
    const int tid = threadIdx.x;
    const float* src = g_V + (size_t)bh * kS * 64;
#pragma unroll
    for (int i = 0; i < 16; i++) {
        int idx = tid + i * 256;
        int r = idx >> 6, c = idx & 63;
        tile[r][c] = src[(size_t)(s0 + r) * 64 + c];
    }
    __syncthreads();
#pragma unroll
    for (int i = 0; i < 16; i++) {
        int idx = tid + i * 256;
        int d = idx >> 6, ss = idx & 63;
        float v = tile[ss][d];
        __nv_bfloat16 hi = __float2bfloat16(v);
        __nv_bfloat16 lo = __float2bfloat16(v - __bfloat162float(hi));
        size_t o = ((size_t)bh * 64 + d) * kS + s0 + ss;
        g_VThi[o] = hi;
        g_VTlo[o] = lo;
    }
}

// ---------------------------------------------------------------------------
// HMMA helpers
// ---------------------------------------------------------------------------
__device__ __forceinline__ void mma16816(float* d, const uint32_t* a,
                                         uint32_t b0, uint32_t b1) {
    asm volatile(
        "mma.sync.aligned.m16n8k16.row.col.f32.bf16.bf16.f32 "
        "{%0,%1,%2,%3}, {%4,%5,%6,%7}, {%8,%9}, {%0,%1,%2,%3};"
        : "+f"(d[0]), "+f"(d[1]), "+f"(d[2]), "+f"(d[3])
        : "r"(a[0]), "r"(a[1]), "r"(a[2]), "r"(a[3]), "r"(b0), "r"(b1));
}
#define LDSM_X4(r, addr) \
    asm volatile("ldmatrix.sync.aligned.m8n8.x4.shared.b16 {%0,%1,%2,%3}, [%4];" \
        : "=r"((r)[0]), "=r"((r)[1]), "=r"((r)[2]), "=r"((r)[3]) : "r"(addr))

// ---------------------------------------------------------------------------
// HMMA split-bf16 GEMM — 2-stage mainloop IDENTICAL to the round-11 passing
// kernel (static smem, two syncs per chunk). Only the epilogue is new:
// OMODE 0: C[row*1024+n]=Carg.  OMODE 1: n<1024 -> Qhi/Qlo (bf16 hi/lo),
//          <2048 -> Khi/Klo, else V fp32 (all in [B,H,S,64] layout).
// ---------------------------------------------------------------------------
template <int OMODE>
__global__ __launch_bounds__(256)
void gemmH(float* __restrict__ Carg)
{
    __shared__ __align__(128) char smem[2 * 20480];

    const int tid    = threadIdx.x;
    const int lane   = tid & 31;
    const int wid    = tid >> 5;
    const int warp_m = wid & 3;
    const int warp_n = wid >> 2;
    const int bn     = blockIdx.x * 128;
    const int bm     = blockIdx.y * 128;
    const uint32_t sbase = smem_u32(smem);

    const __nv_bfloat16* AP[3] = {g_xhi, g_xhi, g_xlo};
    const __nv_bfloat16* BP[3] = {g_whi, g_wlo, g_whi};

    float acc[2][8][4];
#pragma unroll
    for (int i = 0; i < 2; i++)
#pragma unroll
        for (int j = 0; j < 8; j++)
#pragma unroll
            for (int t = 0; t < 4; t++) acc[i][j][t] = 0.f;

    auto issue = [&](int stage, int chunk) {
        const __nv_bfloat16* Ap = AP[chunk >> 5];
        const __nv_bfloat16* Bp = BP[chunk >> 5];
        const int k0 = (chunk & 31) * 32;
        const uint32_t sA = sbase + stage * 20480;
        const uint32_t sB = sA + 10240;
#pragma unroll
        for (int i = 0; i < 2; i++) {
            int idx = tid + i * 256;
            int r = idx >> 2, c = idx & 3;
            const void* ga = Ap + (size_t)(bm + r) * 1024 + k0 + c * 8;
            asm volatile("cp.async.cg.shared.global [%0], [%1], 16;"
                         :: "r"(sA + r * 80 + c * 16), "l"(ga));
            const void* gb = Bp + (size_t)(bn + r) * 1024 + k0 + c * 8;
            asm volatile("cp.async.cg.shared.global [%0], [%1], 16;"
                         :: "r"(sB + r * 80 + c * 16), "l"(gb));
        }
        asm volatile("cp.async.commit_group;" ::: "memory");
    };

    issue(0, 0);

    for (int c = 0; c < 96; c++) {
        if (c + 1 < 96) {
            issue((c + 1) & 1, c + 1);
            asm volatile("cp.async.wait_group 1;" ::: "memory");
        } else {
            asm volatile("cp.async.wait_group 0;" ::: "memory");
        }
        __syncthreads();

        const uint32_t sA = sbase + (c & 1) * 20480;
        const uint32_t sB = sA + 10240;

        uint32_t a[2][2][4];
#pragma unroll
        for (int mt = 0; mt < 2; mt++)
#pragma unroll
            for (int ks = 0; ks < 2; ks++) {
                uint32_t ad = sA + (warp_m * 32 + mt * 16 + (lane & 15)) * 80
                            + ks * 32 + (lane >> 4) * 16;
                LDSM_X4(a[mt][ks], ad);
            }
        uint32_t b[4][2][4];
#pragma unroll
        for (int ng = 0; ng < 4; ng++)
#pragma unroll
            for (int ks = 0; ks < 2; ks++) {
                uint32_t bd = sB + (warp_n * 64 + ng * 16 + ((lane >> 4) << 3) + (lane & 7)) * 80
                            + ks * 32 + ((lane >> 3) & 1) * 16;
                LDSM_X4(b[ng][ks], bd);
            }
#pragma unroll
        for (int mt = 0; mt < 2; mt++)
#pragma unroll
            for (int ng = 0; ng < 4; ng++)
#pragma unroll
                for (int ks = 0; ks < 2; ks++) {
                    mma16816(acc[mt][ng * 2 + 0], a[mt][ks], b[ng][ks][0], b[ng][ks][1]);
                    mma16816(acc[mt][ng * 2 + 1], a[mt][ks], b[ng][ks][2], b[ng][ks][3]);
                }
        __syncthreads();
    }

    // ---- epilogue (new: fused bf16 hi/lo writes for Q/K) ----
    const int tq = lane >> 2;
    const int tr = (lane & 3) * 2;
    const int which = bn >> 10;                    // 0=Q 1=K 2=V (OMODE1)
    const int head  = ((bn & 1023) >> 6) + warp_n;

#pragma unroll
    for (int mt = 0; mt < 2; mt++)
#pragma unroll
        for (int half = 0; half < 2; half++) {
            int row = bm + warp_m * 32 + mt * 16 + half * 8 + tq;
            if (OMODE == 0) {
                float* p = Carg + (size_t)row * 1024 + bn + warp_n * 64 + tr;
#pragma unroll
                for (int n8 = 0; n8 < 8; n8++) {
                    float2 v = half ? make_float2(acc[mt][n8][2], acc[mt][n8][3])
                                    : make_float2(acc[mt][n8][0], acc[mt][n8][1]);
                    *(float2*)(p + n8 * 8) = v;
                }
            } else {
                int bb = row >> 11, ss = row & 2047;
                size_t off = (((size_t)(bb * kH + head) * kS + ss) << 6) + tr;
                if (which == 2) {
                    float* p = g_V + off;
#pragma unroll
                    for (int n8 = 0; n8 < 8; n8++) {
                        float2 v = half ? make_float2(acc[mt][n8][2], acc[mt][n8][3])
                                        : make_float2(acc[mt][n8][0], acc[mt][n8][1]);
                        *(float2*)(p + n8 * 8) = v;
                    }
                } else {
                    __nv_bfloat16* dh = which ? g_Khi : g_Qhi;
                    __nv_bfloat16* dl = which ? g_Klo : g_Qlo;
#pragma unroll
                    for (int n8 = 0; n8 < 8; n8++) {
                        float vx = half ? acc[mt][n8][2] : acc[mt][n8][0];
                        float vy = half ? acc[mt][n8][3] : acc[mt][n8][1];
                        float hx = __bfloat162float(__float2bfloat16(vx));
                        float hy = __bfloat162float(__float2bfloat16(vy));
                        *(uint32_t*)(dh + off + n8 * 8) = packbf(vx, vy);
                        *(uint32_t*)(dl + off + n8 * 8) = packbf(vx - hx, vy - hy);
                    }
                }
            }
        }
}

// ---------------------------------------------------------------------------
// HMMA causal flash attention, split-bf16 (math identical to round-11 pass;
// epilogue writes ctx hi/lo splits directly into g_xhi/g_xlo).
// ---------------------------------------------------------------------------
__global__ __launch_bounds__(256)
void flash_hmma()
{
    __shared__ __align__(128) char sm[4 * 9216];   // 36864

    const int tid  = threadIdx.x;
    const int lane = tid & 31;
    const int wid  = tid >> 5;
    const int qblk = blockIdx.x;
    const int bh   = blockIdx.y;
    const int b    = bh >> 4;
    const int h    = bh & 15;
    const int qrow0 = qblk * 128 + wid * 16;
    const uint32_t sb = smem_u32(sm);

    // ---- Stage Q (128 rows x 64) hi/lo and load fragments ----
    {
        const __nv_bfloat16* Qh = g_Qhi + ((size_t)bh * kS + qblk * 128) * 64;
        const __nv_bfloat16* Ql = g_Qlo + ((size_t)bh * kS + qblk * 128) * 64;
#pragma unroll
        for (int i = 0; i < 4; i++) {
            int idx = tid + i * 256;
            int r = idx >> 3, c = idx & 7;
            *(uint4*)(sm + r * 144 + c * 16)         = *(const uint4*)(Qh + (size_t)r * 64 + c * 8);
            *(uint4*)(sm + 18432 + r * 144 + c * 16) = *(const uint4*)(Ql + (size_t)r * 64 + c * 8);
        }
    }
    __syncthreads();

    uint32_t qh[4][4], ql[4][4];
#pragma unroll
    for (int ks = 0; ks < 4; ks++) {
        uint32_t ad = sb + (wid * 16 + (lane & 15)) * 144 + ks * 32 + (lane >> 4) * 16;
        LDSM_X4(qh[ks], ad);
        LDSM_X4(ql[ks], ad + 18432);
    }

    float m0 = -1e30f, m1 = -1e30f, l0 = 0.f, l1 = 0.f;
    float ctx[8][4];
#pragma unroll
    for (int j = 0; j < 8; j++)
#pragma unroll
        for (int t = 0; t < 4; t++) ctx[j][t] = 0.f;

    const int ktiles = 2 * qblk + 2;
    const int r0g = qrow0 + (lane >> 2);
    const int r1g = r0g + 8;

    for (int kt = 0; kt < ktiles; kt++) {
        __syncthreads();
        {
            const __nv_bfloat16* Kh = g_Khi + ((size_t)bh * kS + kt * 64) * 64;
            const __nv_bfloat16* Kl = g_Klo + ((size_t)bh * kS + kt * 64) * 64;
            const __nv_bfloat16* Vh = g_VThi + (size_t)bh * 64 * kS + kt * 64;
            const __nv_bfloat16* Vl = g_VTlo + (size_t)bh * 64 * kS + kt * 64;
#pragma unroll
            for (int i = 0; i < 8; i++) {
                int idx = tid + i * 256;
                int buf = idx >> 9, rem = idx & 511;
                int r = rem >> 3, c = rem & 7;
                const uint4* src;
                if      (buf == 0) src = (const uint4*)(Kh + (size_t)r * 64 + c * 8);
                else if (buf == 1) src = (const uint4*)(Kl + (size_t)r * 64 + c * 8);
                else if (buf == 2) src = (const uint4*)(Vh + (size_t)r * kS + c * 8);
                else               src = (const uint4*)(Vl + (size_t)r * kS + c * 8);
                *(uint4*)(sm + buf * 9216 + r * 144 + c * 16) = *src;
            }
        }
        __syncthreads();

        if (qrow0 + 15 < kt * 64) continue;

        float sf[8][4];
#pragma unroll
        for (int j = 0; j < 8; j++)
#pragma unroll
            for (int t = 0; t < 4; t++) sf[j][t] = 0.f;

#pragma unroll
        for (int ks = 0; ks < 4; ks++) {
#pragma unroll
            for (int ng = 0; ng < 4; ng++) {
                uint32_t bd = sb + (ng * 16 + ((lane >> 4) << 3) + (lane & 7)) * 144
                            + ks * 32 + ((lane >> 3) & 1) * 16;
                uint32_t bhif[4], blof[4];
                LDSM_X4(bhif, bd);
                LDSM_X4(blof, bd + 9216);
                mma16816(sf[ng * 2 + 0], qh[ks], bhif[0], bhif[1]);
                mma16816(sf[ng * 2 + 1], qh[ks], bhif[2], bhif[3]);
                mma16816(sf[ng * 2 + 0], qh[ks], blof[0], blof[1]);
                mma16816(sf[ng * 2 + 1], qh[ks], blof[2], blof[3]);
                mma16816(sf[ng * 2 + 0], ql[ks], bhif[0], bhif[1]);
                mma16816(sf[ng * 2 + 1], ql[ks], bhif[2], bhif[3]);
            }
        }

#pragma unroll
        for (int j = 0; j < 8; j++) {
            int kg = kt * 64 + j * 8 + 2 * (lane & 3);
            sf[j][0] = (kg     <= r0g) ? sf[j][0] * 0.125f : -1e30f;
            sf[j][1] = (kg + 1 <= r0g) ? sf[j][1] * 0.125f : -1e30f;
            sf[j][2] = (kg     <= r1g) ? sf[j][2] * 0.125f : -1e30f;
            sf[j][3] = (kg + 1 <= r1g) ? sf[j][3] * 0.125f : -1e30f;
        }

        float rm0 = -1e30f, rm1 = -1e30f;
#pragma unroll
        for (int j = 0; j < 8; j++) {
            rm0 = fmaxf(rm0, fmaxf(sf[j][0], sf[j][1]));
            rm1 = fmaxf(rm1, fmaxf(sf[j][2], sf[j][3]));
        }
        rm0 = fmaxf(rm0, __shfl_xor_sync(0xffffffff, rm0, 1));
        rm0 = fmaxf(rm0, __shfl_xor_sync(0xffffffff, rm0, 2));
        rm1 = fmaxf(rm1, __shfl_xor_sync(0xffffffff, rm1, 1));
        rm1 = fmaxf(rm1, __shfl_xor_sync(0xffffffff, rm1, 2));

        float m0n = fmaxf(m0, rm0), m1n = fmaxf(m1, rm1);
        float sc0 = __expf(m0 - m0n), sc1 = __expf(m1 - m1n);
        m0 = m0n; m1 = m1n;

        float rs0 = 0.f, rs1 = 0.f;
#pragma unroll
        for (int j = 0; j < 8; j++) {
            sf[j][0] = __expf(sf[j][0] - m0);
            sf[j][1] = __expf(sf[j][1] - m0);
            sf[j][2] = __expf(sf[j][2] - m1);
            sf[j][3] = __expf(sf[j][3] - m1);
            rs0 += sf[j][0] + sf[j][1];
            rs1 += sf[j][2] + sf[j][3];
        }
        rs0 += __shfl_xor_sync(0xffffffff, rs0, 1);
        rs0 += __shfl_xor_sync(0xffffffff, rs0, 2);
        rs1 += __shfl_xor_sync(0xffffffff, rs1, 1);
        rs1 += __shfl_xor_sync(0xffffffff, rs1, 2);
        l0 = l0 * sc0 + rs0;
        l1 = l1 * sc1 + rs1;
#pragma unroll
        for (int j = 0; j < 8; j++) {
            ctx[j][0] *= sc0; ctx[j][1] *= sc0;
            ctx[j][2] *= sc1; ctx[j][3] *= sc1;
        }

#pragma unroll
        for (int ks2 = 0; ks2 < 4; ks2++) {
            const int j0 = 2 * ks2, j1 = 2 * ks2 + 1;
            uint32_t ahi[4], alo[4];
            ahi[0] = packbf(sf[j0][0], sf[j0][1]);
            ahi[1] = packbf(sf[j0][2], sf[j0][3]);
            ahi[2] = packbf(sf[j1][0], sf[j1][1]);
            ahi[3] = packbf(sf[j1][2], sf[j1][3]);
            {
                float a0 = sf[j0][0] - __bfloat162float(__float2bfloat16(sf[j0][0]));
                float a1 = sf[j0][1] - __bfloat162float(__float2bfloat16(sf[j0][1]));
                float a2 = sf[j0][2] - __bfloat162float(__float2bfloat16(sf[j0][2]));
                float a3 = sf[j0][3] - __bfloat162float(__float2bfloat16(sf[j0][3]));
                float a4 = sf[j1][0] - __bfloat162float(__float2bfloat16(sf[j1][0]));
                float a5 = sf[j1][1] - __bfloat162float(__float2bfloat16(sf[j1][1]));
                float a6 = sf[j1][2] - __bfloat162float(__float2bfloat16(sf[j1][2]));
                float a7 = sf[j1][3] - __bfloat162float(__float2bfloat16(sf[j1][3]));
                alo[0] = packbf(a0, a1); alo[1] = packbf(a2, a3);
                alo[2] = packbf(a4, a5); alo[3] = packbf(a6, a7);
            }
#pragma unroll
            for (int ng = 0; ng < 4; ng++) {
                uint32_t vd = sb + 18432 + (ng * 16 + ((lane >> 4) << 3) + (lane & 7)) * 144
                            + ks2 * 32 + ((lane >> 3) & 1) * 16;
                uint32_t vhif[4], vlof[4];
                LDSM_X4(vhif, vd);
                LDSM_X4(vlof, vd + 9216);
                mma16816(ctx[ng * 2 + 0], ahi, vhif[0], vhif[1]);
                mma16816(ctx[ng * 2 + 1], ahi, vhif[2], vhif[3]);
                mma16816(ctx[ng * 2 + 0], ahi, vlof[0], vlof[1]);
                mma16816(ctx[ng * 2 + 1], ahi, vlof[2], vlof[3]);
                mma16816(ctx[ng * 2 + 0], alo, vhif[0], vhif[1]);
                mma16816(ctx[ng * 2 + 1], alo, vhif[2], vhif[3]);
            }
        }
    }

    // ---- epilogue: normalize + write ctx hi/lo splits directly ----
    const float inv0 = 1.f / l0, inv1 = 1.f / l1;
#pragma unroll
    for (int j = 0; j < 8; j++) {
        int d = j * 8 + 2 * (lane & 3);
        size_t o0 = (size_t)(b * kS + r0g) * 1024 + h * 64 + d;
        size_t o1 = (size_t)(b * kS + r1g) * 1024 + h * 64 + d;
        float v0 = ctx[j][0] * inv0, v1 = ctx[j][1] * inv0;
        float v2 = ctx[j][2] * inv1, v3 = ctx[j][3] * inv1;
        float h0 = __bfloat162float(__float2bfloat16(v0));
        float h1 = __bfloat162float(__float2bfloat16(v1));
        float h2 = __bfloat162float(__float2bfloat16(v2));
        float h3 = __bfloat162float(__float2bfloat16(v3));
        *(uint32_t*)(g_xhi + o0) = packbf(v0, v1);
        *(uint32_t*)(g_xlo + o0) = packbf(v0 - h0, v1 - h1);
        *(uint32_t*)(g_xhi + o1) = packbf(v2, v3);
        *(uint32_t*)(g_xlo + o1) = packbf(v2 - h2, v3 - h3);
    }
}

// ---------------------------------------------------------------------------
extern "C" void kernel_launch(void* const* d_in, const int* in_sizes, int n_in,
                              void* d_out, int out_size)
{
    const float* x  = (const float*)d_in[0];   // [B,S,D]
    const float* Wq = (const float*)d_in[1];   // [H,D,64]
    const float* Wk = (const float*)d_in[2];
    const float* Wv = (const float*)d_in[3];
    const float* Wo = (const float*)d_in[4];   // [1024,1024]
    float* out = (float*)d_out;

    // x -> bf16 hi/lo split
    cvt_split<<<8192, 256>>>(x);

    // Fused QKV weights -> [3072][1024] K-major split (coalesced, tiled)
    cvt_wT<1><<<dim3(16, 16), 256>>>(Wq, 0);
    cvt_wT<1><<<dim3(16, 16), 256>>>(Wk, 1024);
    cvt_wT<1><<<dim3(16, 16), 256>>>(Wv, 2048);

    // Fused QKV projection: Q,K written directly as bf16 hi/lo; V fp32
    gemmH<1><<<dim3(24, 64), 256>>>(nullptr);

    // V -> transposed bf16 hi/lo
    vt_split<<<dim3(kS / 64, kB * kH), 256>>>();

    // Causal attention on tensor cores -> ctx hi/lo (g_xhi/g_xlo)
    flash_hmma<<<dim3(kS / 128, kB * kH), 256>>>();

    // Output projection
    cvt_wT<0><<<dim3(16, 16), 256>>>(Wo, 0);
    gemmH<0><<<dim3(8, 64), 256>>>(out);
}

// round 17
// speedup vs baseline: 3.7866x; 1.1107x over previous
#include <cuda_runtime.h>
#include <cuda_bf16.h>
#include <math.h>
#include <stdint.h>

// Problem constants
constexpr int kB  = 4;
constexpr int kS  = 2048;
constexpr int kD  = 1024;
constexpr int kH  = 16;

// ---------------------------------------------------------------------------
// Scratch (device globals — no allocation allowed)
// ---------------------------------------------------------------------------
__device__ float g_V[kB * kH * kS * 64];        // [B,H,S,64] fp32 (for transpose)

__device__ __nv_bfloat16 g_xhi[kB * kS * kD];   // A split (x, then ctx) [8192,1024]
__device__ __nv_bfloat16 g_xlo[kB * kS * kD];
__device__ __nv_bfloat16 g_whi[3 * kD * kD];    // B split, [N<=3072][K=1024] K-major
__device__ __nv_bfloat16 g_wlo[3 * kD * kD];

// Attention operands, bf16 hi/lo
__device__ __nv_bfloat16 g_Qhi[kB * kH * kS * 64];   // [B,H,S,64]
__device__ __nv_bfloat16 g_Qlo[kB * kH * kS * 64];
__device__ __nv_bfloat16 g_Khi[kB * kH * kS * 64];
__device__ __nv_bfloat16 g_Klo[kB * kH * kS * 64];
__device__ __nv_bfloat16 g_VThi[kB * kH * 64 * kS];  // [B,H,64(d),S]
__device__ __nv_bfloat16 g_VTlo[kB * kH * 64 * kS];

__device__ __forceinline__ uint32_t smem_u32(const void* p) {
    uint32_t a;
    asm("{ .reg .u64 t; cvta.to.shared.u64 t, %1; cvt.u32.u64 %0, t; }" : "=r"(a) : "l"(p));
    return a;
}
__device__ __forceinline__ uint32_t packbf(float a, float b) {
    __nv_bfloat162 t = __floats2bfloat162_rn(a, b);
    return *(uint32_t*)&t;
}

// ---------------------------------------------------------------------------
// Conversion kernels (identical to round-15 pass, QKV weight cvt fused by z)
// ---------------------------------------------------------------------------
__global__ __launch_bounds__(256)
void cvt_split(const float* __restrict__ src)
{
    int i = blockIdx.x * 256 + threadIdx.x;       // float4 index
    float4 v = ((const float4*)src)[i];
    __nv_bfloat16 h0 = __float2bfloat16(v.x), h1 = __float2bfloat16(v.y);
    __nv_bfloat16 h2 = __float2bfloat16(v.z), h3 = __float2bfloat16(v.w);
    __nv_bfloat16 l0 = __float2bfloat16(v.x - __bfloat162float(h0));
    __nv_bfloat16 l1 = __float2bfloat16(v.y - __bfloat162float(h1));
    __nv_bfloat16 l2 = __float2bfloat16(v.z - __bfloat162float(h2));
    __nv_bfloat16 l3 = __float2bfloat16(v.w - __bfloat162float(h3));
    ((__nv_bfloat162*)g_xhi)[i * 2 + 0] = __nv_bfloat162(h0, h1);
    ((__nv_bfloat162*)g_xhi)[i * 2 + 1] = __nv_bfloat162(h2, h3);
    ((__nv_bfloat162*)g_xlo)[i * 2 + 0] = __nv_bfloat162(l0, l1);
    ((__nv_bfloat162*)g_xlo)[i * 2 + 1] = __nv_bfloat162(l2, l3);
}

__global__ __launch_bounds__(256)
void cvt_wT3(const float* __restrict__ Wq, const float* __restrict__ Wk,
             const float* __restrict__ Wv)
{
    __shared__ float tile[64][65];
    const int kt = blockIdx.x;
    const int hz = blockIdx.y;
    const int z  = blockIdx.z;
    const float* W = (z == 0) ? Wq : (z == 1) ? Wk : Wv;
    const int n_off = z * 1024;
    const int tid = threadIdx.x;
#pragma unroll
    for (int i = 0; i < 16; i++) {
        int e = tid + i * 256;
        int r = e >> 6, c = e & 63;
        tile[r][c] = W[((size_t)hz * 1024 + kt * 64 + r) * 64 + c];
    }
    __syncthreads();
#pragma unroll
    for (int i = 0; i < 16; i++) {
        int e = tid + i * 256;
        int rr = e >> 6, cc = e & 63;
        float v = tile[cc][rr];
        __nv_bfloat16 hi = __float2bfloat16(v);
        __nv_bfloat16 lo = __float2bfloat16(v - __bfloat162float(hi));
        int n = n_off + hz * 64 + rr;
        int k = kt * 64 + cc;
        g_whi[(size_t)n * 1024 + k] = hi;
        g_wlo[(size_t)n * 1024 + k] = lo;
    }
}

__global__ __launch_bounds__(256)
void cvt_wTo(const float* __restrict__ W)
{
    __shared__ float tile[64][65];
    const int kt = blockIdx.x;
    const int hz = blockIdx.y;
    const int tid = threadIdx.x;
#pragma unroll
    for (int i = 0; i < 16; i++) {
        int e = tid + i * 256;
        int r = e >> 6, c = e & 63;
        tile[r][c] = W[(size_t)(kt * 64 + r) * 1024 + hz * 64 + c];
    }
    __syncthreads();
#pragma unroll
    for (int i = 0; i < 16; i++) {
        int e = tid + i * 256;
        int rr = e >> 6, cc = e & 63;
        float v = tile[cc][rr];
        __nv_bfloat16 hi = __float2bfloat16(v);
        __nv_bfloat16 lo = __float2bfloat16(v - __bfloat162float(hi));
        int n = hz * 64 + rr;
        int k = kt * 64 + cc;
        g_whi[(size_t)n * 1024 + k] = hi;
        g_wlo[(size_t)n * 1024 + k] = lo;
    }
}

__global__ __launch_bounds__(256)
void vt_split()
{
    __shared__ float tile[64][65];
    const int s0 = blockIdx.x * 64;
    const int bh = blockIdx.y;
    const int tid = threadIdx.x;
    const float* src = g_V + (size_t)bh * kS * 64;
#pragma unroll
    for (int i = 0; i < 16; i++) {
        int idx = tid + i * 256;
        int r = idx >> 6, c = idx & 63;
        tile[r][c] = src[(size_t)(s0 + r) * 64 + c];
    }
    __syncthreads();
#pragma unroll
    for (int i = 0; i < 16; i++) {
        int idx = tid + i * 256;
        int d = idx >> 6, ss = idx & 63;
        float v = tile[ss][d];
        __nv_bfloat16 hi = __float2bfloat16(v);
        __nv_bfloat16 lo = __float2bfloat16(v - __bfloat162float(hi));
        size_t o = ((size_t)bh * 64 + d) * kS + s0 + ss;
        g_VThi[o] = hi;
        g_VTlo[o] = lo;
    }
}

// ---------------------------------------------------------------------------
// HMMA helpers
// ---------------------------------------------------------------------------
__device__ __forceinline__ void mma16816(float* d, const uint32_t* a,
                                         uint32_t b0, uint32_t b1) {
    asm volatile(
        "mma.sync.aligned.m16n8k16.row.col.f32.bf16.bf16.f32 "
        "{%0,%1,%2,%3}, {%4,%5,%6,%7}, {%8,%9}, {%0,%1,%2,%3};"
        : "+f"(d[0]), "+f"(d[1]), "+f"(d[2]), "+f"(d[3])
        : "r"(a[0]), "r"(a[1]), "r"(a[2]), "r"(a[3]), "r"(b0), "r"(b1));
}
#define LDSM_X4(r, addr) \
    asm volatile("ldmatrix.sync.aligned.m8n8.x4.shared.b16 {%0,%1,%2,%3}, [%4];" \
        : "=r"((r)[0]), "=r"((r)[1]), "=r"((r)[2]), "=r"((r)[3]) : "r"(addr))

// XOR swizzle for 64B-pitch tiles: 4 x 16B segments per row,
// stored segment = c ^ ((row>>1)&3). Conflict-free for cp.async stores
// and for both A/B ldmatrix phase patterns (verified by bank-base enumeration).
__device__ __forceinline__ uint32_t swz(int row, int seg) {
    return (uint32_t)(row * 64 + ((seg ^ ((row >> 1) & 3)) << 4));
}

// ---------------------------------------------------------------------------
// HMMA split-bf16 GEMM, 3-stage cp.async, ONE sync per chunk, STATIC smem.
// CTA 128x128, BK=32, 8 warps (32x64 each). 3 x 16KB stages = 48KB static.
// OMODE 0: C[row*1024+n]=Carg.  OMODE 1: n<1024 -> Qhi/Qlo, <2048 -> Khi/Klo,
//          else V fp32 (all in [B,H,S,64] layout).
// ---------------------------------------------------------------------------
constexpr int kStageBytes = 16384;               // A 128x64B + B 128x64B

template <int OMODE>
__global__ __launch_bounds__(256)
void gemmH(float* __restrict__ Carg)
{
    __shared__ __align__(128) char smem[3 * kStageBytes];   // 49152 = 48KB

    const int tid    = threadIdx.x;
    const int lane   = tid & 31;
    const int wid    = tid >> 5;
    const int warp_m = wid & 3;
    const int warp_n = wid >> 2;
    const int bn     = blockIdx.x * 128;
    const int bm     = blockIdx.y * 128;
    const uint32_t sbase = smem_u32(smem);

    const __nv_bfloat16* AP[3] = {g_xhi, g_xhi, g_xlo};
    const __nv_bfloat16* BP[3] = {g_whi, g_wlo, g_whi};

    float acc[2][8][4];
#pragma unroll
    for (int i = 0; i < 2; i++)
#pragma unroll
        for (int j = 0; j < 8; j++)
#pragma unroll
            for (int t = 0; t < 4; t++) acc[i][j][t] = 0.f;

    auto issue = [&](int stage, int chunk) {
        const __nv_bfloat16* Ap = AP[chunk >> 5];
        const __nv_bfloat16* Bp = BP[chunk >> 5];
        const int k0 = (chunk & 31) * 32;
        const uint32_t sA = sbase + stage * kStageBytes;
        const uint32_t sB = sA + 8192;
#pragma unroll
        for (int i = 0; i < 2; i++) {
            int idx = tid + i * 256;          // 0..511
            int r = idx >> 2, c = idx & 3;    // row 0..127, seg 0..3
            const void* ga = Ap + (size_t)(bm + r) * 1024 + k0 + c * 8;
            asm volatile("cp.async.cg.shared.global [%0], [%1], 16;"
                         :: "r"(sA + swz(r, c)), "l"(ga));
            const void* gb = Bp + (size_t)(bn + r) * 1024 + k0 + c * 8;
            asm volatile("cp.async.cg.shared.global [%0], [%1], 16;"
                         :: "r"(sB + swz(r, c)), "l"(gb));
        }
        asm volatile("cp.async.commit_group;" ::: "memory");
    };

    issue(0, 0);
    issue(1, 1);

    for (int c = 0; c < 96; c++) {
        if (c + 1 < 96) { asm volatile("cp.async.wait_group 1;" ::: "memory"); }
        else            { asm volatile("cp.async.wait_group 0;" ::: "memory"); }
        __syncthreads();                       // stage c ready; buf (c+2)%3 free
        if (c + 2 < 96) issue((c + 2) % 3, c + 2);

        const uint32_t sA = sbase + (c % 3) * kStageBytes;
        const uint32_t sB = sA + 8192;

        uint32_t a[2][2][4];
#pragma unroll
        for (int mt = 0; mt < 2; mt++)
#pragma unroll
            for (int ks = 0; ks < 2; ks++) {
                int row = warp_m * 32 + mt * 16 + (lane & 15);
                int seg = ks * 2 + (lane >> 4);
                LDSM_X4(a[mt][ks], sA + swz(row, seg));
            }
        uint32_t b[4][2][4];
#pragma unroll
        for (int ng = 0; ng < 4; ng++)
#pragma unroll
            for (int ks = 0; ks < 2; ks++) {
                int row = warp_n * 64 + ng * 16 + ((lane >> 4) << 3) + (lane & 7);
                int seg = ks * 2 + ((lane >> 3) & 1);
                LDSM_X4(b[ng][ks], sB + swz(row, seg));
            }
#pragma unroll
        for (int mt = 0; mt < 2; mt++)
#pragma unroll
            for (int ng = 0; ng < 4; ng++)
#pragma unroll
                for (int ks = 0; ks < 2; ks++) {
                    mma16816(acc[mt][ng * 2 + 0], a[mt][ks], b[ng][ks][0], b[ng][ks][1]);
                    mma16816(acc[mt][ng * 2 + 1], a[mt][ks], b[ng][ks][2], b[ng][ks][3]);
                }
    }

    // ---- epilogue (identical to round-15 pass) ----
    const int tq = lane >> 2;
    const int tr = (lane & 3) * 2;
    const int which = bn >> 10;                    // 0=Q 1=K 2=V (OMODE1)
    const int head  = ((bn & 1023) >> 6) + warp_n;

#pragma unroll
    for (int mt = 0; mt < 2; mt++)
#pragma unroll
        for (int half = 0; half < 2; half++) {
            int row = bm + warp_m * 32 + mt * 16 + half * 8 + tq;
            if (OMODE == 0) {
                float* p = Carg + (size_t)row * 1024 + bn + warp_n * 64 + tr;
#pragma unroll
                for (int n8 = 0; n8 < 8; n8++) {
                    float2 v = half ? make_float2(acc[mt][n8][2], acc[mt][n8][3])
                                    : make_float2(acc[mt][n8][0], acc[mt][n8][1]);
                    *(float2*)(p + n8 * 8) = v;
                }
            } else {
                int bb = row >> 11, ss = row & 2047;
                size_t off = (((size_t)(bb * kH + head) * kS + ss) << 6) + tr;
                if (which == 2) {
                    float* p = g_V + off;
#pragma unroll
                    for (int n8 = 0; n8 < 8; n8++) {
                        float2 v = half ? make_float2(acc[mt][n8][2], acc[mt][n8][3])
                                        : make_float2(acc[mt][n8][0], acc[mt][n8][1]);
                        *(float2*)(p + n8 * 8) = v;
                    }
                } else {
                    __nv_bfloat16* dh = which ? g_Khi : g_Qhi;
                    __nv_bfloat16* dl = which ? g_Klo : g_Qlo;
#pragma unroll
                    for (int n8 = 0; n8 < 8; n8++) {
                        float vx = half ? acc[mt][n8][2] : acc[mt][n8][0];
                        float vy = half ? acc[mt][n8][3] : acc[mt][n8][1];
                        float hx = __bfloat162float(__float2bfloat16(vx));
                        float hy = __bfloat162float(__float2bfloat16(vy));
                        *(uint32_t*)(dh + off + n8 * 8) = packbf(vx, vy);
                        *(uint32_t*)(dl + off + n8 * 8) = packbf(vx - hx, vy - hy);
                    }
                }
            }
        }
}

// ---------------------------------------------------------------------------
// HMMA causal flash attention, split-bf16 (identical to round-15 pass)
// ---------------------------------------------------------------------------
__global__ __launch_bounds__(256)
void flash_hmma()
{
    __shared__ __align__(128) char sm[4 * 9216];   // 36864

    const int tid  = threadIdx.x;
    const int lane = tid & 31;
    const int wid  = tid >> 5;
    const int qblk = blockIdx.x;
    const int bh   = blockIdx.y;
    const int b    = bh >> 4;
    const int h    = bh & 15;
    const int qrow0 = qblk * 128 + wid * 16;
    const uint32_t sb = smem_u32(sm);

    {
        const __nv_bfloat16* Qh = g_Qhi + ((size_t)bh * kS + qblk * 128) * 64;
        const __nv_bfloat16* Ql = g_Qlo + ((size_t)bh * kS + qblk * 128) * 64;
#pragma unroll
        for (int i = 0; i < 4; i++) {
            int idx = tid + i * 256;
            int r = idx >> 3, c = idx & 7;
            *(uint4*)(sm + r * 144 + c * 16)         = *(const uint4*)(Qh + (size_t)r * 64 + c * 8);
            *(uint4*)(sm + 18432 + r * 144 + c * 16) = *(const uint4*)(Ql + (size_t)r * 64 + c * 8);
        }
    }
    __syncthreads();

    uint32_t qh[4][4], ql[4][4];
#pragma unroll
    for (int ks = 0; ks < 4; ks++) {
        uint32_t ad = sb + (wid * 16 + (lane & 15)) * 144 + ks * 32 + (lane >> 4) * 16;
        LDSM_X4(qh[ks], ad);
        LDSM_X4(ql[ks], ad + 18432);
    }

    float m0 = -1e30f, m1 = -1e30f, l0 = 0.f, l1 = 0.f;
    float ctx[8][4];
#pragma unroll
    for (int j = 0; j < 8; j++)
#pragma unroll
        for (int t = 0; t < 4; t++) ctx[j][t] = 0.f;

    const int ktiles = 2 * qblk + 2;
    const int r0g = qrow0 + (lane >> 2);
    const int r1g = r0g + 8;

    for (int kt = 0; kt < ktiles; kt++) {
        __syncthreads();
        {
            const __nv_bfloat16* Kh = g_Khi + ((size_t)bh * kS + kt * 64) * 64;
            const __nv_bfloat16* Kl = g_Klo + ((size_t)bh * kS + kt * 64) * 64;
            const __nv_bfloat16* Vh = g_VThi + (size_t)bh * 64 * kS + kt * 64;
            const __nv_bfloat16* Vl = g_VTlo + (size_t)bh * 64 * kS + kt * 64;
#pragma unroll
            for (int i = 0; i < 8; i++) {
                int idx = tid + i * 256;
                int buf = idx >> 9, rem = idx & 511;
                int r = rem >> 3, c = rem & 7;
                const uint4* src;
                if      (buf == 0) src = (const uint4*)(Kh + (size_t)r * 64 + c * 8);
                else if (buf == 1) src = (const uint4*)(Kl + (size_t)r * 64 + c * 8);
                else if (buf == 2) src = (const uint4*)(Vh + (size_t)r * kS + c * 8);
                else               src = (const uint4*)(Vl + (size_t)r * kS + c * 8);
                *(uint4*)(sm + buf * 9216 + r * 144 + c * 16) = *src;
            }
        }
        __syncthreads();

        if (qrow0 + 15 < kt * 64) continue;

        float sf[8][4];
#pragma unroll
        for (int j = 0; j < 8; j++)
#pragma unroll
            for (int t = 0; t < 4; t++) sf[j][t] = 0.f;

#pragma unroll
        for (int ks = 0; ks < 4; ks++) {
#pragma unroll
            for (int ng = 0; ng < 4; ng++) {
                uint32_t bd = sb + (ng * 16 + ((lane >> 4) << 3) + (lane & 7)) * 144
                            + ks * 32 + ((lane >> 3) & 1) * 16;
                uint32_t bhif[4], blof[4];
                LDSM_X4(bhif, bd);
                LDSM_X4(blof, bd + 9216);
                mma16816(sf[ng * 2 + 0], qh[ks], bhif[0], bhif[1]);
                mma16816(sf[ng * 2 + 1], qh[ks], bhif[2], bhif[3]);
                mma16816(sf[ng * 2 + 0], qh[ks], blof[0], blof[1]);
                mma16816(sf[ng * 2 + 1], qh[ks], blof[2], blof[3]);
                mma16816(sf[ng * 2 + 0], ql[ks], bhif[0], bhif[1]);
                mma16816(sf[ng * 2 + 1], ql[ks], bhif[2], bhif[3]);
            }
        }

#pragma unroll
        for (int j = 0; j < 8; j++) {
            int kg = kt * 64 + j * 8 + 2 * (lane & 3);
            sf[j][0] = (kg     <= r0g) ? sf[j][0] * 0.125f : -1e30f;
            sf[j][1] = (kg + 1 <= r0g) ? sf[j][1] * 0.125f : -1e30f;
            sf[j][2] = (kg     <= r1g) ? sf[j][2] * 0.125f : -1e30f;
            sf[j][3] = (kg + 1 <= r1g) ? sf[j][3] * 0.125f : -1e30f;
        }

        float rm0 = -1e30f, rm1 = -1e30f;
#pragma unroll
        for (int j = 0; j < 8; j++) {
            rm0 = fmaxf(rm0, fmaxf(sf[j][0], sf[j][1]));
            rm1 = fmaxf(rm1, fmaxf(sf[j][2], sf[j][3]));
        }
        rm0 = fmaxf(rm0, __shfl_xor_sync(0xffffffff, rm0, 1));
        rm0 = fmaxf(rm0, __shfl_xor_sync(0xffffffff, rm0, 2));
        rm1 = fmaxf(rm1, __shfl_xor_sync(0xffffffff, rm1, 1));
        rm1 = fmaxf(rm1, __shfl_xor_sync(0xffffffff, rm1, 2));

        float m0n = fmaxf(m0, rm0), m1n = fmaxf(m1, rm1);
        float sc0 = __expf(m0 - m0n), sc1 = __expf(m1 - m1n);
        m0 = m0n; m1 = m1n;

        float rs0 = 0.f, rs1 = 0.f;
#pragma unroll
        for (int j = 0; j < 8; j++) {
            sf[j][0] = __expf(sf[j][0] - m0);
            sf[j][1] = __expf(sf[j][1] - m0);
            sf[j][2] = __expf(sf[j][2] - m1);
            sf[j][3] = __expf(sf[j][3] - m1);
            rs0 += sf[j][0] + sf[j][1];
            rs1 += sf[j][2] + sf[j][3];
        }
        rs0 += __shfl_xor_sync(0xffffffff, rs0, 1);
        rs0 += __shfl_xor_sync(0xffffffff, rs0, 2);
        rs1 += __shfl_xor_sync(0xffffffff, rs1, 1);
        rs1 += __shfl_xor_sync(0xffffffff, rs1, 2);
        l0 = l0 * sc0 + rs0;
        l1 = l1 * sc1 + rs1;
#pragma unroll
        for (int j = 0; j < 8; j++) {
            ctx[j][0] *= sc0; ctx[j][1] *= sc0;
            ctx[j][2] *= sc1; ctx[j][3] *= sc1;
        }

#pragma unroll
        for (int ks2 = 0; ks2 < 4; ks2++) {
            const int j0 = 2 * ks2, j1 = 2 * ks2 + 1;
            uint32_t ahi[4], alo[4];
            ahi[0] = packbf(sf[j0][0], sf[j0][1]);
            ahi[1] = packbf(sf[j0][2], sf[j0][3]);
            ahi[2] = packbf(sf[j1][0], sf[j1][1]);
            ahi[3] = packbf(sf[j1][2], sf[j1][3]);
            {
                float a0 = sf[j0][0] - __bfloat162float(__float2bfloat16(sf[j0][0]));
                float a1 = sf[j0][1] - __bfloat162float(__float2bfloat16(sf[j0][1]));
                float a2 = sf[j0][2] - __bfloat162float(__float2bfloat16(sf[j0][2]));
                float a3 = sf[j0][3] - __bfloat162float(__float2bfloat16(sf[j0][3]));
                float a4 = sf[j1][0] - __bfloat162float(__float2bfloat16(sf[j1][0]));
                float a5 = sf[j1][1] - __bfloat162float(__float2bfloat16(sf[j1][1]));
                float a6 = sf[j1][2] - __bfloat162float(__float2bfloat16(sf[j1][2]));
                float a7 = sf[j1][3] - __bfloat162float(__float2bfloat16(sf[j1][3]));
                alo[0] = packbf(a0, a1); alo[1] = packbf(a2, a3);
                alo[2] = packbf(a4, a5); alo[3] = packbf(a6, a7);
            }
#pragma unroll
            for (int ng = 0; ng < 4; ng++) {
                uint32_t vd = sb + 18432 + (ng * 16 + ((lane >> 4) << 3) + (lane & 7)) * 144
                            + ks2 * 32 + ((lane >> 3) & 1) * 16;
                uint32_t vhif[4], vlof[4];
                LDSM_X4(vhif, vd);
                LDSM_X4(vlof, vd + 9216);
                mma16816(ctx[ng * 2 + 0], ahi, vhif[0], vhif[1]);
                mma16816(ctx[ng * 2 + 1], ahi, vhif[2], vhif[3]);
                mma16816(ctx[ng * 2 + 0], ahi, vlof[0], vlof[1]);
                mma16816(ctx[ng * 2 + 1], ahi, vlof[2], vlof[3]);
                mma16816(ctx[ng * 2 + 0], alo, vhif[0], vhif[1]);
                mma16816(ctx[ng * 2 + 1], alo, vhif[2], vhif[3]);
            }
        }
    }

    const float inv0 = 1.f / l0, inv1 = 1.f / l1;
#pragma unroll
    for (int j = 0; j < 8; j++) {
        int d = j * 8 + 2 * (lane & 3);
        size_t o0 = (size_t)(b * kS + r0g) * 1024 + h * 64 + d;
        size_t o1 = (size_t)(b * kS + r1g) * 1024 + h * 64 + d;
        float v0 = ctx[j][0] * inv0, v1 = ctx[j][1] * inv0;
        float v2 = ctx[j][2] * inv1, v3 = ctx[j][3] * inv1;
        float h0 = __bfloat162float(__float2bfloat16(v0));
        float h1 = __bfloat162float(__float2bfloat16(v1));
        float h2 = __bfloat162float(__float2bfloat16(v2));
        float h3 = __bfloat162float(__float2bfloat16(v3));
        *(uint32_t*)(g_xhi + o0) = packbf(v0, v1);
        *(uint32_t*)(g_xlo + o0) = packbf(v0 - h0, v1 - h1);
        *(uint32_t*)(g_xhi + o1) = packbf(v2, v3);
        *(uint32_t*)(g_xlo + o1) = packbf(v2 - h2, v3 - h3);
    }
}

// ---------------------------------------------------------------------------
extern "C" void kernel_launch(void* const* d_in, const int* in_sizes, int n_in,
                              void* d_out, int out_size)
{
    const float* x  = (const float*)d_in[0];   // [B,S,D]
    const float* Wq = (const float*)d_in[1];   // [H,D,64]
    const float* Wk = (const float*)d_in[2];
    const float* Wv = (const float*)d_in[3];
    const float* Wo = (const float*)d_in[4];   // [1024,1024]
    float* out = (float*)d_out;

    // x -> bf16 hi/lo split
    cvt_split<<<8192, 256>>>(x);

    // Fused QKV weights -> [3072][1024] K-major split (one launch, grid z)
    cvt_wT3<<<dim3(16, 16, 3), 256>>>(Wq, Wk, Wv);

    // Fused QKV projection: Q,K written directly as bf16 hi/lo; V fp32
    gemmH<1><<<dim3(24, 64), 256>>>(nullptr);

    // V -> transposed bf16 hi/lo
    vt_split<<<dim3(kS / 64, kB * kH), 256>>>();

    // Causal attention on tensor cores -> ctx hi/lo (g_xhi/g_xlo)
    flash_hmma<<<dim3(kS / 128, kB * kH), 256>>>();

    // Output projection
    cvt_wTo<<<dim3(16, 16), 256>>>(Wo);
    gemmH<0><<<dim3(8, 64), 256>>>(out);
}